// round 2
// baseline (speedup 1.0000x reference)
#include <cuda_runtime.h>
#include <cuda_bf16.h>
#include <math.h>

// Problem constants
#define BB 64
#define SS 256
#define DD 512
#define HH 8
#define DH 64
#define DFF 2048
#define VV 128
#define LL 6
#define M_TOK (BB*SS)          // 16384 rows

// ---------------------------------------------------------------------------
// Scratch (device globals; no allocation allowed)
// ---------------------------------------------------------------------------
__device__ float g_x   [M_TOK*DD];     // residual stream
__device__ float g_big [M_TOK*DFF];    // qkv (1536 cols) / ff1 (2048 cols)
__device__ float g_attn[M_TOK*DD];     // attention output (pre out-proj)
__device__ float g_sub [M_TOK*DD];     // sublayer output
__device__ float g_mem [BB*DD];        // z @ proj_w^T
__device__ float g_cav [BB*DD];        // mem @ Wv^T
__device__ float g_ca  [BB*DD];        // cross-attn per-batch vector

// ---------------------------------------------------------------------------
// Embedding: x[b,s,:] = emb[tgt[b,s]] + pos[s]   (float4 vectorized)
// ---------------------------------------------------------------------------
__global__ void embed_kernel(const int* __restrict__ tgt,
                             const float* __restrict__ emb,
                             const float* __restrict__ pos,
                             float* __restrict__ x) {
    int row = blockIdx.x;             // b*S + s
    int d4  = threadIdx.x;            // 128 threads, 4 floats each
    int tok = tgt[row];
    int s   = row & (SS - 1);
    float4 e = ((const float4*)(emb + (size_t)tok*DD))[d4];
    float4 p = ((const float4*)(pos + (size_t)s*DD))[d4];
    float4 o = make_float4(e.x+p.x, e.y+p.y, e.z+p.z, e.w+p.w);
    ((float4*)(x + (size_t)row*DD))[d4] = o;
}

// ---------------------------------------------------------------------------
// Generic NT GEMM: C[m,n] = sum_k A[m*K+k]*B[n*K+k] + bias[n]  (opt ReLU)
// BM=BN=128, BK=8, 256 threads, 8x8 per thread. N % 128 == 0, K % 8 == 0.
// M may be ragged: A-tile rows are clamped (safe re-read), stores guarded.
// ---------------------------------------------------------------------------
__global__ void __launch_bounds__(256)
gemm_nt(const float* __restrict__ A, const float* __restrict__ B,
        const float* __restrict__ bias, float* __restrict__ C,
        int M, int N, int K, int relu) {
    __shared__ float As[8][128];
    __shared__ float Bs[8][128];

    const int bm = blockIdx.y * 128;
    const int bn = blockIdx.x * 128;
    const int tid = threadIdx.x;
    const int tx = tid & 15;          // 0..15
    const int ty = tid >> 4;          // 0..15
    const int lr = tid >> 1;          // load row 0..127
    const int lc = (tid & 1) * 4;     // load col 0 or 4

    const int arow = min(bm + lr, M - 1);   // clamped; junk rows never stored
    const int brow = bn + lr;

    float acc[8][8];
    #pragma unroll
    for (int i = 0; i < 8; i++)
        #pragma unroll
        for (int j = 0; j < 8; j++) acc[i][j] = 0.f;

    for (int kt = 0; kt < K; kt += 8) {
        {
            float4 v = *(const float4*)(A + (size_t)arow*K + kt + lc);
            As[lc+0][lr] = v.x; As[lc+1][lr] = v.y;
            As[lc+2][lr] = v.z; As[lc+3][lr] = v.w;
        }
        {
            float4 v = *(const float4*)(B + (size_t)brow*K + kt + lc);
            Bs[lc+0][lr] = v.x; Bs[lc+1][lr] = v.y;
            Bs[lc+2][lr] = v.z; Bs[lc+3][lr] = v.w;
        }
        __syncthreads();

        #pragma unroll
        for (int k = 0; k < 8; k++) {
            float a[8], b[8];
            #pragma unroll
            for (int i = 0; i < 8; i++) a[i] = As[k][ty*8 + i];
            #pragma unroll
            for (int j = 0; j < 8; j++) b[j] = Bs[k][tx*8 + j];
            #pragma unroll
            for (int i = 0; i < 8; i++)
                #pragma unroll
                for (int j = 0; j < 8; j++)
                    acc[i][j] = fmaf(a[i], b[j], acc[i][j]);
        }
        __syncthreads();
    }

    #pragma unroll
    for (int i = 0; i < 8; i++) {
        int row = bm + ty*8 + i;
        if (row >= M) continue;
        #pragma unroll
        for (int j = 0; j < 8; j++) {
            int col = bn + tx*8 + j;
            float v = acc[i][j] + bias[col];
            if (relu) v = fmaxf(v, 0.f);
            C[(size_t)row*N + col] = v;
        }
    }
}

// ---------------------------------------------------------------------------
// Fused causal self-attention.
// qkv: rows = b*S+s, cols = [q(512) | k(512) | v(512)], head h at offset h*64.
// One CTA per (b,h). Q,K,V staged in smem (pad 65 -> conflict free).
// 8 warps, each warp processes 32 queries serially; warp-wide softmax.
// ---------------------------------------------------------------------------
#define ATTN_PAD 65
#define ATTN_SMEM ((3*SS*ATTN_PAD + 8*SS) * 4)

__global__ void __launch_bounds__(256)
attn_kernel(const float* __restrict__ qkv, float* __restrict__ out) {
    extern __shared__ float sm[];
    float* Qs = sm;
    float* Ks = sm + SS*ATTN_PAD;
    float* Vs = sm + 2*SS*ATTN_PAD;
    float* Ps = sm + 3*SS*ATTN_PAD;   // [8 warps][256]

    const int b = blockIdx.x >> 3;
    const int h = blockIdx.x & 7;
    const int tid = threadIdx.x;
    const float* base = qkv + (size_t)(b*SS)*(3*DD) + h*DH;

    for (int i = tid; i < SS*DH; i += 256) {
        int s = i >> 6, d = i & 63;
        size_t g = (size_t)s*(3*DD) + d;
        Qs[s*ATTN_PAD + d] = base[g];
        Ks[s*ATTN_PAD + d] = base[g + DD];
        Vs[s*ATTN_PAD + d] = base[g + 2*DD];
    }
    __syncthreads();

    const int warp = tid >> 5, lane = tid & 31;
    float* ps = Ps + warp*SS;
    const float scale = 0.125f;   // 1/sqrt(64)

    for (int q = warp; q < SS; q += 8) {
        float sreg[8];
        float m = -1e30f;
        const float* qp = &Qs[q*ATTN_PAD];
        #pragma unroll
        for (int kk = 0; kk < 8; kk++) {
            int key = kk*32 + lane;
            float a = -1e30f;
            if (key <= q) {
                const float* kp = &Ks[key*ATTN_PAD];
                float acc = 0.f;
                #pragma unroll
                for (int d = 0; d < DH; d++) acc = fmaf(qp[d], kp[d], acc);
                a = acc * scale;
            }
            sreg[kk] = a;
            m = fmaxf(m, a);
        }
        #pragma unroll
        for (int o = 16; o; o >>= 1) m = fmaxf(m, __shfl_xor_sync(~0u, m, o));
        float sum = 0.f;
        #pragma unroll
        for (int kk = 0; kk < 8; kk++) {
            float p = __expf(sreg[kk] - m);
            sreg[kk] = p; sum += p;
        }
        #pragma unroll
        for (int o = 16; o; o >>= 1) sum += __shfl_xor_sync(~0u, sum, o);
        float inv = 1.f / sum;
        #pragma unroll
        for (int kk = 0; kk < 8; kk++) ps[kk*32 + lane] = sreg[kk] * inv;
        __syncwarp();

        // PV: lane owns dims (lane, lane+32)
        float o0 = 0.f, o1 = 0.f;
        for (int key = 0; key <= q; key++) {
            float p = ps[key];
            o0 = fmaf(p, Vs[key*ATTN_PAD + lane],      o0);
            o1 = fmaf(p, Vs[key*ATTN_PAD + lane + 32], o1);
        }
        float* op = out + (size_t)(b*SS + q)*DD + h*DH;
        op[lane]      = o0;
        op[lane + 32] = o1;
        __syncwarp();
    }
}

// ---------------------------------------------------------------------------
// Fused residual add + LayerNorm (in place on x).
// bcast=1: residual is per-batch (row -> row/S).
// ---------------------------------------------------------------------------
__global__ void __launch_bounds__(128)
add_ln_kernel(float* __restrict__ x, const float* __restrict__ r,
              const float* __restrict__ g, const float* __restrict__ bt,
              int bcast) {
    int row = blockIdx.x;
    const float* rp = r + (bcast ? (size_t)(row >> 8)*DD : (size_t)row*DD);
    float* xp = x + (size_t)row*DD;
    int t = threadIdx.x;

    float v[4];
    float sum = 0.f;
    #pragma unroll
    for (int i = 0; i < 4; i++) {
        int d = t + i*128;
        v[i] = xp[d] + rp[d];
        sum += v[i];
    }
    __shared__ float red1[4], red2[4];
    #pragma unroll
    for (int o = 16; o; o >>= 1) sum += __shfl_xor_sync(~0u, sum, o);
    if ((t & 31) == 0) red1[t >> 5] = sum;
    __syncthreads();
    float mean = (red1[0] + red1[1] + red1[2] + red1[3]) * (1.f/512.f);

    float var = 0.f;
    #pragma unroll
    for (int i = 0; i < 4; i++) {
        float d = v[i] - mean;
        var = fmaf(d, d, var);
    }
    #pragma unroll
    for (int o = 16; o; o >>= 1) var += __shfl_xor_sync(~0u, var, o);
    if ((t & 31) == 0) red2[t >> 5] = var;
    __syncthreads();
    float rs = rsqrtf((red2[0] + red2[1] + red2[2] + red2[3]) * (1.f/512.f) + 1e-5f);

    #pragma unroll
    for (int i = 0; i < 4; i++) {
        int d = t + i*128;
        xp[d] = (v[i] - mean) * rs * g[d] + bt[d];
    }
}

// ---------------------------------------------------------------------------
// Launch
// ---------------------------------------------------------------------------
extern "C" void kernel_launch(void* const* d_in, const int* in_sizes, int n_in,
                              void* d_out, int out_size) {
    const float* z      = (const float*)d_in[0];
    const int*   tgt    = (const int*)  d_in[1];
    const float* emb    = (const float*)d_in[2];
    const float* pos    = (const float*)d_in[3];
    const float* proj_w = (const float*)d_in[4];
    const float* proj_b = (const float*)d_in[5];
    const float* sa_w   = (const float*)d_in[6];
    const float* sa_b   = (const float*)d_in[7];
    const float* sa_ow  = (const float*)d_in[8];
    const float* sa_ob  = (const float*)d_in[9];
    const float* ca_w   = (const float*)d_in[10];
    const float* ca_b   = (const float*)d_in[11];
    const float* ca_ow  = (const float*)d_in[12];
    const float* ca_ob  = (const float*)d_in[13];
    const float* ln1_s  = (const float*)d_in[14];
    const float* ln1_b  = (const float*)d_in[15];
    const float* ln2_s  = (const float*)d_in[16];
    const float* ln2_b  = (const float*)d_in[17];
    const float* ln3_s  = (const float*)d_in[18];
    const float* ln3_b  = (const float*)d_in[19];
    const float* ff1_w  = (const float*)d_in[20];
    const float* ff1_b  = (const float*)d_in[21];
    const float* ff2_w  = (const float*)d_in[22];
    const float* ff2_b  = (const float*)d_in[23];
    const float* fc_w   = (const float*)d_in[24];
    const float* fc_b   = (const float*)d_in[25];
    float* out = (float*)d_out;

    float *x, *big, *attnb, *sub, *mem, *cav, *ca;
    cudaGetSymbolAddress((void**)&x,     g_x);
    cudaGetSymbolAddress((void**)&big,   g_big);
    cudaGetSymbolAddress((void**)&attnb, g_attn);
    cudaGetSymbolAddress((void**)&sub,   g_sub);
    cudaGetSymbolAddress((void**)&mem,   g_mem);
    cudaGetSymbolAddress((void**)&cav,   g_cav);
    cudaGetSymbolAddress((void**)&ca,    g_ca);

    cudaFuncSetAttribute(attn_kernel,
                         cudaFuncAttributeMaxDynamicSharedMemorySize, ATTN_SMEM);

    // embedding + memory projection
    embed_kernel<<<M_TOK, 128>>>(tgt, emb, pos, x);
    gemm_nt<<<dim3(DD/128, 1), 256>>>(z, proj_w, proj_b, mem, BB, DD, DD, 0);

    for (int l = 0; l < LL; l++) {
        const float* sawl  = sa_w  + (size_t)l*3*DD*DD;
        const float* sabl  = sa_b  + (size_t)l*3*DD;
        const float* saowl = sa_ow + (size_t)l*DD*DD;
        const float* saobl = sa_ob + (size_t)l*DD;
        const float* cawv  = ca_w  + (size_t)l*3*DD*DD + (size_t)2*DD*DD;
        const float* cabv  = ca_b  + (size_t)l*3*DD + 2*DD;
        const float* caowl = ca_ow + (size_t)l*DD*DD;
        const float* caobl = ca_ob + (size_t)l*DD;

        // self-attention
        gemm_nt<<<dim3(3*DD/128, M_TOK/128), 256>>>(x, sawl, sabl, big,
                                                    M_TOK, 3*DD, DD, 0);
        attn_kernel<<<BB*HH, 256, ATTN_SMEM>>>(big, attnb);
        gemm_nt<<<dim3(DD/128, M_TOK/128), 256>>>(attnb, saowl, saobl, sub,
                                                  M_TOK, DD, DD, 0);
        add_ln_kernel<<<M_TOK, 128>>>(x, sub, ln1_s + l*DD, ln1_b + l*DD, 0);

        // cross-attention over a length-1 memory == per-batch vector
        gemm_nt<<<dim3(DD/128, 1), 256>>>(mem, cawv, cabv, cav, BB, DD, DD, 0);
        gemm_nt<<<dim3(DD/128, 1), 256>>>(cav, caowl, caobl, ca, BB, DD, DD, 0);
        add_ln_kernel<<<M_TOK, 128>>>(x, ca, ln2_s + l*DD, ln2_b + l*DD, 1);

        // feed-forward
        gemm_nt<<<dim3(DFF/128, M_TOK/128), 256>>>(x, ff1_w + (size_t)l*DFF*DD,
                                                   ff1_b + l*DFF, big,
                                                   M_TOK, DFF, DD, 1);
        gemm_nt<<<dim3(DD/128, M_TOK/128), 256>>>(big, ff2_w + (size_t)l*DD*DFF,
                                                  ff2_b + l*DD, sub,
                                                  M_TOK, DD, DFF, 0);
        add_ln_kernel<<<M_TOK, 128>>>(x, sub, ln3_s + l*DD, ln3_b + l*DD, 0);
    }

    // final classifier
    gemm_nt<<<dim3(VV/128, M_TOK/128), 256>>>(x, fc_w, fc_b, out,
                                              M_TOK, VV, DD, 0);
}

// round 4
// speedup vs baseline: 2.1674x; 2.1674x over previous
#include <cuda_runtime.h>
#include <cuda_bf16.h>
#include <math.h>
#include <stdint.h>

// Problem constants
#define BB 64
#define SS 256
#define DD 512
#define HH 8
#define DH 64
#define DFF 2048
#define VV 128
#define LL 6
#define M_TOK (BB*SS)          // 16384 rows

// ---------------------------------------------------------------------------
// Scratch (device globals; no allocation allowed)
// ---------------------------------------------------------------------------
__device__ float g_x   [M_TOK*DD];
__device__ float g_big [M_TOK*DFF];
__device__ float g_attn[M_TOK*DD];
__device__ float g_sub [M_TOK*DD];
__device__ float g_mem [BB*DD];
__device__ float g_cav [BB*DD];
__device__ float g_ca  [BB*DD];

// bf16 hi/lo pools (plain row-major)
__device__ __nv_bfloat16 g_ahi[(size_t)M_TOK*DFF];
__device__ __nv_bfloat16 g_alo[(size_t)M_TOK*DFF];
#define O_SAW  0u
#define O_SAOW 4718592u
#define O_FF1  6291456u
#define O_FF2  12582912u
#define O_FC   18874368u
#define WPOOL_E 18940032u
__device__ __nv_bfloat16 g_whi[WPOOL_E];
__device__ __nv_bfloat16 g_wlo[WPOOL_E];

// ---------------------------------------------------------------------------
// Helpers
// ---------------------------------------------------------------------------
__device__ __forceinline__ uint32_t smem_u32(const void* p) {
    uint32_t a;
    asm("{ .reg .u64 t; cvta.to.shared.u64 t, %1; cvt.u32.u64 %0, t; }"
        : "=r"(a) : "l"(p));
    return a;
}
__device__ __forceinline__ void cp_async16(uint32_t dst, const void* src) {
    asm volatile("cp.async.cg.shared.global [%0], [%1], 16;"
                 :: "r"(dst), "l"(src));
}
#define CP_COMMIT() asm volatile("cp.async.commit_group;" ::: "memory")
#define CP_WAIT1()  asm volatile("cp.async.wait_group 1;" ::: "memory")

__device__ __forceinline__ void ldm_x4(uint32_t* r, uint32_t addr) {
    asm volatile("ldmatrix.sync.aligned.m8n8.x4.shared.b16 {%0,%1,%2,%3}, [%4];"
                 : "=r"(r[0]), "=r"(r[1]), "=r"(r[2]), "=r"(r[3]) : "r"(addr));
}
__device__ __forceinline__ void mma_bf16(float* c, const uint32_t* a,
                                         const uint32_t* b) {
    asm volatile(
        "mma.sync.aligned.m16n8k16.row.col.f32.bf16.bf16.f32 "
        "{%0,%1,%2,%3}, {%4,%5,%6,%7}, {%8,%9}, {%0,%1,%2,%3};"
        : "+f"(c[0]), "+f"(c[1]), "+f"(c[2]), "+f"(c[3])
        : "r"(a[0]), "r"(a[1]), "r"(a[2]), "r"(a[3]), "r"(b[0]), "r"(b[1]));
}

// ---------------------------------------------------------------------------
// Embedding
// ---------------------------------------------------------------------------
__global__ void embed_kernel(const int* __restrict__ tgt,
                             const float* __restrict__ emb,
                             const float* __restrict__ pos,
                             float* __restrict__ x) {
    int row = blockIdx.x;
    int d4  = threadIdx.x;
    int tok = tgt[row];
    int s   = row & (SS - 1);
    float4 e = ((const float4*)(emb + (size_t)tok*DD))[d4];
    float4 p = ((const float4*)(pos + (size_t)s*DD))[d4];
    ((float4*)(x + (size_t)row*DD))[d4] =
        make_float4(e.x+p.x, e.y+p.y, e.z+p.z, e.w+p.w);
}

// ---------------------------------------------------------------------------
// fp32 -> bf16 hi/lo split (plain row-major). n must be multiple of 1024.
// ---------------------------------------------------------------------------
__device__ __forceinline__ uint32_t pack2bf(float a, float b) {
    __nv_bfloat162 t = __floats2bfloat162_rn(a, b);
    return *(uint32_t*)&t;
}
__global__ void __launch_bounds__(256)
conv_pair(const float* __restrict__ src, __nv_bfloat16* __restrict__ hi,
          __nv_bfloat16* __restrict__ lo) {
    size_t i = (size_t)blockIdx.x * 256 + threadIdx.x;   // float4 index
    float4 v = ((const float4*)src)[i];
    float xs[4] = {v.x, v.y, v.z, v.w};
    float hf[4], lf[4];
    #pragma unroll
    for (int e = 0; e < 4; e++) {
        __nv_bfloat16 h = __float2bfloat16_rn(xs[e]);
        hf[e] = __bfloat162float(h);
        lf[e] = xs[e] - hf[e];
    }
    ((uint2*)hi)[i] = make_uint2(pack2bf(hf[0],hf[1]), pack2bf(hf[2],hf[3]));
    ((uint2*)lo)[i] = make_uint2(pack2bf(lf[0],lf[1]), pack2bf(lf[2],lf[3]));
}

// ---------------------------------------------------------------------------
// HMMA bf16x3 GEMM: C[M,N] = A[M,K] @ B[N,K]^T + bias (opt ReLU)
// A,B row-major bf16 (hi/lo pools). CTA 128x128, 8 warps (2x4), warp 64x32.
// K chunk 64, 2-stage cp.async pipeline, SW128-xor smem swizzle + ldmatrix.
// M, N, K multiples of 128/128/64. Accum fp32 in registers.
// ---------------------------------------------------------------------------
#define HSTAGE 65536           // bytes per stage: Ahi 16K | Alo 16K | Bhi 16K | Blo 16K
#define HSMEM  (2*HSTAGE)

__global__ void __launch_bounds__(256, 1)
gemm_hmma(const __nv_bfloat16* __restrict__ Ahi,
          const __nv_bfloat16* __restrict__ Alo,
          const __nv_bfloat16* __restrict__ Bhi,
          const __nv_bfloat16* __restrict__ Blo,
          const float* __restrict__ bias, float* __restrict__ C,
          int N, int K, int relu) {
    extern __shared__ char smg[];
    const uint32_t sa = smem_u32(smg);
    const int tid = threadIdx.x;
    const int wid = tid >> 5, lane = tid & 31;
    const int wM = wid >> 2, wN = wid & 3;       // 2 x 4 warps
    const int bm = blockIdx.y * 128;
    const int bn = blockIdx.x * 128;
    const int kc = K >> 6;

    float acc[4][4][4];
    #pragma unroll
    for (int i = 0; i < 4; i++)
        #pragma unroll
        for (int j = 0; j < 4; j++)
            #pragma unroll
            for (int e = 0; e < 4; e++) acc[i][j][e] = 0.f;

    // ---- loader lambda: stage s <- K-chunk kk ----
    auto load_stage = [&](int s, int kk) {
        uint32_t stg = sa + s*HSTAGE;
        #pragma unroll
        for (int i = tid; i < 2048; i += 256) {       // A hi+lo
            int pool = i >> 10, r = (i >> 3) & 127, c = i & 7;
            const __nv_bfloat16* g =
                (pool ? Alo : Ahi) + (size_t)(bm + r)*K + kk*64 + c*8;
            uint32_t d = stg + pool*16384 + r*128 + ((c*16) ^ ((r & 7) << 4));
            cp_async16(d, g);
        }
        #pragma unroll
        for (int i = tid; i < 2048; i += 256) {       // B hi+lo
            int pool = i >> 10, r = (i >> 3) & 127, c = i & 7;
            const __nv_bfloat16* g =
                (pool ? Blo : Bhi) + (size_t)(bn + r)*K + kk*64 + c*8;
            uint32_t d = stg + 32768 + pool*16384 + r*128 +
                         ((c*16) ^ ((r & 7) << 4));
            cp_async16(d, g);
        }
    };

    load_stage(0, 0); CP_COMMIT();
    load_stage(1, 1); CP_COMMIT();

    // per-thread ldmatrix address components
    const int laneA_row = lane & 15;              // + mf*16 + wM*64
    const int laneA_b   = (lane >> 4) << 4;       // + ks*32
    const int laneB_row = ((lane >> 4) << 3) + (lane & 7);  // + nf2*16 + wN*32
    const int laneB_b   = ((lane >> 3) & 1) << 4;

    for (int ch = 0; ch < kc; ch++) {
        CP_WAIT1();
        __syncthreads();
        uint32_t stg = sa + (ch & 1)*HSTAGE;

        #pragma unroll
        for (int ks = 0; ks < 4; ks++) {
            uint32_t ah[4][4], al[4][4], bh[2][4], bl[2][4];
            #pragma unroll
            for (int mf = 0; mf < 4; mf++) {
                int r = wM*64 + mf*16 + laneA_row;
                uint32_t b = (uint32_t)(ks*32 + laneA_b);
                uint32_t off = r*128 + (b ^ ((r & 7) << 4));
                ldm_x4(ah[mf], stg + off);
                ldm_x4(al[mf], stg + 16384 + off);
            }
            #pragma unroll
            for (int nf2 = 0; nf2 < 2; nf2++) {
                int r = wN*32 + nf2*16 + laneB_row;
                uint32_t b = (uint32_t)(ks*32 + laneB_b);
                uint32_t off = r*128 + (b ^ ((r & 7) << 4));
                ldm_x4(bh[nf2], stg + 32768 + off);
                ldm_x4(bl[nf2], stg + 49152 + off);
            }
            #pragma unroll
            for (int mf = 0; mf < 4; mf++)
                #pragma unroll
                for (int nf = 0; nf < 4; nf++) {
                    const uint32_t* bhf = &bh[nf >> 1][(nf & 1)*2];
                    const uint32_t* blf = &bl[nf >> 1][(nf & 1)*2];
                    mma_bf16(acc[mf][nf], ah[mf], bhf);
                    mma_bf16(acc[mf][nf], ah[mf], blf);
                    mma_bf16(acc[mf][nf], al[mf], bhf);
                }
        }
        __syncthreads();
        if (ch + 2 < kc) load_stage(ch & 1, ch + 2);
        CP_COMMIT();
    }

    // ---- epilogue ----
    const int gid = lane >> 2, tig = lane & 3;
    #pragma unroll
    for (int mf = 0; mf < 4; mf++) {
        int r0 = bm + wM*64 + mf*16 + gid;
        #pragma unroll
        for (int nf = 0; nf < 4; nf++) {
            int col = bn + wN*32 + nf*8 + tig*2;
            float bx = __ldg(bias + col), by = __ldg(bias + col + 1);
            float2 v0 = make_float2(acc[mf][nf][0] + bx, acc[mf][nf][1] + by);
            float2 v1 = make_float2(acc[mf][nf][2] + bx, acc[mf][nf][3] + by);
            if (relu) {
                v0.x = fmaxf(v0.x, 0.f); v0.y = fmaxf(v0.y, 0.f);
                v1.x = fmaxf(v1.x, 0.f); v1.y = fmaxf(v1.y, 0.f);
            }
            *(float2*)(C + (size_t)r0*N + col)       = v0;
            *(float2*)(C + (size_t)(r0 + 8)*N + col) = v1;
        }
    }
}

// ---------------------------------------------------------------------------
// fp32 SIMT NT GEMM (tiny B=64 cross-attn GEMMs)
// ---------------------------------------------------------------------------
__global__ void __launch_bounds__(256)
gemm_nt(const float* __restrict__ A, const float* __restrict__ B,
        const float* __restrict__ bias, float* __restrict__ C,
        int M, int N, int K, int relu) {
    __shared__ float As[8][128];
    __shared__ float Bs[8][128];

    const int bm = blockIdx.y * 128;
    const int bn = blockIdx.x * 128;
    const int tid = threadIdx.x;
    const int tx = tid & 15;
    const int ty = tid >> 4;
    const int lr = tid >> 1;
    const int lc = (tid & 1) * 4;

    const int arow = min(bm + lr, M - 1);
    const int brow = bn + lr;

    float acc[8][8];
    #pragma unroll
    for (int i = 0; i < 8; i++)
        #pragma unroll
        for (int j = 0; j < 8; j++) acc[i][j] = 0.f;

    for (int kt = 0; kt < K; kt += 8) {
        {
            float4 v = *(const float4*)(A + (size_t)arow*K + kt + lc);
            As[lc+0][lr] = v.x; As[lc+1][lr] = v.y;
            As[lc+2][lr] = v.z; As[lc+3][lr] = v.w;
        }
        {
            float4 v = *(const float4*)(B + (size_t)brow*K + kt + lc);
            Bs[lc+0][lr] = v.x; Bs[lc+1][lr] = v.y;
            Bs[lc+2][lr] = v.z; Bs[lc+3][lr] = v.w;
        }
        __syncthreads();
        #pragma unroll
        for (int k = 0; k < 8; k++) {
            float a[8], b[8];
            #pragma unroll
            for (int i = 0; i < 8; i++) a[i] = As[k][ty*8 + i];
            #pragma unroll
            for (int j = 0; j < 8; j++) b[j] = Bs[k][tx*8 + j];
            #pragma unroll
            for (int i = 0; i < 8; i++)
                #pragma unroll
                for (int j = 0; j < 8; j++)
                    acc[i][j] = fmaf(a[i], b[j], acc[i][j]);
        }
        __syncthreads();
    }
    #pragma unroll
    for (int i = 0; i < 8; i++) {
        int row = bm + ty*8 + i;
        if (row >= M) continue;
        #pragma unroll
        for (int j = 0; j < 8; j++) {
            int col = bn + tx*8 + j;
            float v = acc[i][j] + bias[col];
            if (relu) v = fmaxf(v, 0.f);
            C[(size_t)row*N + col] = v;
        }
    }
}

// ---------------------------------------------------------------------------
// Fused causal self-attention (unchanged passing version)
// ---------------------------------------------------------------------------
#define ATTN_PAD 65
#define ATTN_SMEM ((3*SS*ATTN_PAD + 8*SS) * 4)

__global__ void __launch_bounds__(256)
attn_kernel(const float* __restrict__ qkv, float* __restrict__ out) {
    extern __shared__ float smf[];
    float* Qs = smf;
    float* Ks = smf + SS*ATTN_PAD;
    float* Vs = smf + 2*SS*ATTN_PAD;
    float* Ps = smf + 3*SS*ATTN_PAD;

    const int b = blockIdx.x >> 3;
    const int h = blockIdx.x & 7;
    const int tid = threadIdx.x;
    const float* base = qkv + (size_t)(b*SS)*(3*DD) + h*DH;

    for (int i = tid; i < SS*DH; i += 256) {
        int s = i >> 6, d = i & 63;
        size_t g = (size_t)s*(3*DD) + d;
        Qs[s*ATTN_PAD + d] = base[g];
        Ks[s*ATTN_PAD + d] = base[g + DD];
        Vs[s*ATTN_PAD + d] = base[g + 2*DD];
    }
    __syncthreads();

    const int warp = tid >> 5, lane = tid & 31;
    float* ps = Ps + warp*SS;
    const float scale = 0.125f;

    for (int q = warp; q < SS; q += 8) {
        float sreg[8];
        float m = -1e30f;
        const float* qp = &Qs[q*ATTN_PAD];
        #pragma unroll
        for (int kk = 0; kk < 8; kk++) {
            int key = kk*32 + lane;
            float a = -1e30f;
            if (key <= q) {
                const float* kp = &Ks[key*ATTN_PAD];
                float acc = 0.f;
                #pragma unroll
                for (int d = 0; d < DH; d++) acc = fmaf(qp[d], kp[d], acc);
                a = acc * scale;
            }
            sreg[kk] = a;
            m = fmaxf(m, a);
        }
        #pragma unroll
        for (int o = 16; o; o >>= 1) m = fmaxf(m, __shfl_xor_sync(~0u, m, o));
        float sum = 0.f;
        #pragma unroll
        for (int kk = 0; kk < 8; kk++) {
            float p = __expf(sreg[kk] - m);
            sreg[kk] = p; sum += p;
        }
        #pragma unroll
        for (int o = 16; o; o >>= 1) sum += __shfl_xor_sync(~0u, sum, o);
        float inv = 1.f / sum;
        #pragma unroll
        for (int kk = 0; kk < 8; kk++) ps[kk*32 + lane] = sreg[kk] * inv;
        __syncwarp();

        float o0 = 0.f, o1 = 0.f;
        for (int key = 0; key <= q; key++) {
            float p = ps[key];
            o0 = fmaf(p, Vs[key*ATTN_PAD + lane],      o0);
            o1 = fmaf(p, Vs[key*ATTN_PAD + lane + 32], o1);
        }
        float* op = out + (size_t)(b*SS + q)*DD + h*DH;
        op[lane]      = o0;
        op[lane + 32] = o1;
        __syncwarp();
    }
}

// ---------------------------------------------------------------------------
// Fused residual add + LayerNorm
// ---------------------------------------------------------------------------
__global__ void __launch_bounds__(128)
add_ln_kernel(float* __restrict__ x, const float* __restrict__ r,
              const float* __restrict__ g, const float* __restrict__ bt,
              int bcast) {
    int row = blockIdx.x;
    const float* rp = r + (bcast ? (size_t)(row >> 8)*DD : (size_t)row*DD);
    float* xp = x + (size_t)row*DD;
    int t = threadIdx.x;

    float v[4];
    float sum = 0.f;
    #pragma unroll
    for (int i = 0; i < 4; i++) {
        int d = t + i*128;
        v[i] = xp[d] + rp[d];
        sum += v[i];
    }
    __shared__ float red1[4], red2[4];
    #pragma unroll
    for (int o = 16; o; o >>= 1) sum += __shfl_xor_sync(~0u, sum, o);
    if ((t & 31) == 0) red1[t >> 5] = sum;
    __syncthreads();
    float mean = (red1[0] + red1[1] + red1[2] + red1[3]) * (1.f/512.f);

    float var = 0.f;
    #pragma unroll
    for (int i = 0; i < 4; i++) {
        float d = v[i] - mean;
        var = fmaf(d, d, var);
    }
    #pragma unroll
    for (int o = 16; o; o >>= 1) var += __shfl_xor_sync(~0u, var, o);
    if ((t & 31) == 0) red2[t >> 5] = var;
    __syncthreads();
    float rs = rsqrtf((red2[0] + red2[1] + red2[2] + red2[3]) * (1.f/512.f) + 1e-5f);

    #pragma unroll
    for (int i = 0; i < 4; i++) {
        int d = t + i*128;
        xp[d] = (v[i] - mean) * rs * g[d] + bt[d];
    }
}

// ---------------------------------------------------------------------------
// Launch
// ---------------------------------------------------------------------------
extern "C" void kernel_launch(void* const* d_in, const int* in_sizes, int n_in,
                              void* d_out, int out_size) {
    const float* z      = (const float*)d_in[0];
    const int*   tgt    = (const int*)  d_in[1];
    const float* emb    = (const float*)d_in[2];
    const float* pos    = (const float*)d_in[3];
    const float* proj_w = (const float*)d_in[4];
    const float* proj_b = (const float*)d_in[5];
    const float* sa_w   = (const float*)d_in[6];
    const float* sa_b   = (const float*)d_in[7];
    const float* sa_ow  = (const float*)d_in[8];
    const float* sa_ob  = (const float*)d_in[9];
    const float* ca_w   = (const float*)d_in[10];
    const float* ca_b   = (const float*)d_in[11];
    const float* ca_ow  = (const float*)d_in[12];
    const float* ca_ob  = (const float*)d_in[13];
    const float* ln1_s  = (const float*)d_in[14];
    const float* ln1_b  = (const float*)d_in[15];
    const float* ln2_s  = (const float*)d_in[16];
    const float* ln2_b  = (const float*)d_in[17];
    const float* ln3_s  = (const float*)d_in[18];
    const float* ln3_b  = (const float*)d_in[19];
    const float* ff1_w  = (const float*)d_in[20];
    const float* ff1_b  = (const float*)d_in[21];
    const float* ff2_w  = (const float*)d_in[22];
    const float* ff2_b  = (const float*)d_in[23];
    const float* fc_w   = (const float*)d_in[24];
    const float* fc_b   = (const float*)d_in[25];
    float* out = (float*)d_out;

    float *x, *big, *attnb, *sub, *mem, *cav, *ca;
    __nv_bfloat16 *ahi, *alo, *whi, *wlo;
    cudaGetSymbolAddress((void**)&x,     g_x);
    cudaGetSymbolAddress((void**)&big,   g_big);
    cudaGetSymbolAddress((void**)&attnb, g_attn);
    cudaGetSymbolAddress((void**)&sub,   g_sub);
    cudaGetSymbolAddress((void**)&mem,   g_mem);
    cudaGetSymbolAddress((void**)&cav,   g_cav);
    cudaGetSymbolAddress((void**)&ca,    g_ca);
    cudaGetSymbolAddress((void**)&ahi,   g_ahi);
    cudaGetSymbolAddress((void**)&alo,   g_alo);
    cudaGetSymbolAddress((void**)&whi,   g_whi);
    cudaGetSymbolAddress((void**)&wlo,   g_wlo);

    cudaFuncSetAttribute(attn_kernel,
                         cudaFuncAttributeMaxDynamicSharedMemorySize, ATTN_SMEM);
    cudaFuncSetAttribute(gemm_hmma,
                         cudaFuncAttributeMaxDynamicSharedMemorySize, HSMEM);

    // ---- weight conversion (whole arrays, plain row-major) ----
    conv_pair<<<6*3*DD*DD/1024,  256>>>(sa_w,  whi + O_SAW,  wlo + O_SAW);
    conv_pair<<<6*DD*DD/1024,    256>>>(sa_ow, whi + O_SAOW, wlo + O_SAOW);
    conv_pair<<<6*DFF*DD/1024,   256>>>(ff1_w, whi + O_FF1,  wlo + O_FF1);
    conv_pair<<<6*DD*DFF/1024,   256>>>(ff2_w, whi + O_FF2,  wlo + O_FF2);
    conv_pair<<<VV*DD/1024,      256>>>(fc_w,  whi + O_FC,   wlo + O_FC);

    // ---- embedding + memory projection ----
    embed_kernel<<<M_TOK, 128>>>(tgt, emb, pos, x);
    gemm_nt<<<dim3(DD/128, 1), 256>>>(z, proj_w, proj_b, mem, BB, DD, DD, 0);

    for (int l = 0; l < LL; l++) {
        const float* sabl  = sa_b  + (size_t)l*3*DD;
        const float* saobl = sa_ob + (size_t)l*DD;
        const float* cawv  = ca_w  + (size_t)l*3*DD*DD + (size_t)2*DD*DD;
        const float* cabv  = ca_b  + (size_t)l*3*DD + 2*DD;
        const float* caowl = ca_ow + (size_t)l*DD*DD;
        const float* caobl = ca_ob + (size_t)l*DD;
        size_t o_qkv = O_SAW  + (size_t)l*3*DD*DD;
        size_t o_ow  = O_SAOW + (size_t)l*DD*DD;
        size_t o_ff1 = O_FF1  + (size_t)l*DFF*DD;
        size_t o_ff2 = O_FF2  + (size_t)l*DD*DFF;

        // self-attention
        conv_pair<<<M_TOK*DD/1024, 256>>>(x, ahi, alo);
        gemm_hmma<<<dim3(12, 128), 256, HSMEM>>>(ahi, alo, whi + o_qkv,
                                                 wlo + o_qkv, sabl, big,
                                                 3*DD, DD, 0);
        attn_kernel<<<BB*HH, 256, ATTN_SMEM>>>(big, attnb);
        conv_pair<<<M_TOK*DD/1024, 256>>>(attnb, ahi, alo);
        gemm_hmma<<<dim3(4, 128), 256, HSMEM>>>(ahi, alo, whi + o_ow,
                                                wlo + o_ow, saobl, sub,
                                                DD, DD, 0);
        add_ln_kernel<<<M_TOK, 128>>>(x, sub, ln1_s + l*DD, ln1_b + l*DD, 0);

        // cross-attention over length-1 memory == per-batch vector
        gemm_nt<<<dim3(DD/128, 1), 256>>>(mem, cawv, cabv, cav, BB, DD, DD, 0);
        gemm_nt<<<dim3(DD/128, 1), 256>>>(cav, caowl, caobl, ca, BB, DD, DD, 0);
        add_ln_kernel<<<M_TOK, 128>>>(x, ca, ln2_s + l*DD, ln2_b + l*DD, 1);

        // feed-forward
        conv_pair<<<M_TOK*DD/1024, 256>>>(x, ahi, alo);
        gemm_hmma<<<dim3(16, 128), 256, HSMEM>>>(ahi, alo, whi + o_ff1,
                                                 wlo + o_ff1, ff1_b + l*DFF,
                                                 big, DFF, DD, 1);
        conv_pair<<<M_TOK*DFF/1024, 256>>>(big, ahi, alo);
        gemm_hmma<<<dim3(4, 128), 256, HSMEM>>>(ahi, alo, whi + o_ff2,
                                                wlo + o_ff2, ff2_b + l*DD,
                                                sub, DD, DFF, 0);
        add_ln_kernel<<<M_TOK, 128>>>(x, sub, ln3_s + l*DD, ln3_b + l*DD, 0);
    }

    // final classifier (N=128)
    conv_pair<<<M_TOK*DD/1024, 256>>>(x, ahi, alo);
    gemm_hmma<<<dim3(1, 128), 256, HSMEM>>>(ahi, alo, whi + O_FC, wlo + O_FC,
                                            fc_b, out, VV, DD, 0);
}

// round 5
// speedup vs baseline: 3.0033x; 1.3857x over previous
#include <cuda_runtime.h>
#include <cuda_bf16.h>
#include <math.h>
#include <stdint.h>

#define BB 64
#define SS 256
#define DD 512
#define HH 8
#define DH 64
#define DFF 2048
#define VV 128
#define LL 6
#define M_TOK (BB*SS)

// ---------------------------------------------------------------------------
// Scratch
// ---------------------------------------------------------------------------
__device__ float g_x  [M_TOK*DD];
__device__ float g_sub[M_TOK*DD];
__device__ float g_mem[BB*DD];
__device__ float g_cav[BB*DD];
__device__ float g_ca [BB*DD];

// activation bf16 hi/lo pools
__device__ __nv_bfloat16 g_ahi[(size_t)M_TOK*DD];    // x / attnb hi
__device__ __nv_bfloat16 g_alo[(size_t)M_TOK*DD];
__device__ __nv_bfloat16 g_qhi[(size_t)M_TOK*3*DD];  // qkv hi
__device__ __nv_bfloat16 g_qlo[(size_t)M_TOK*3*DD];
__device__ __nv_bfloat16 g_fhi[(size_t)M_TOK*DFF];   // ff1 out hi
__device__ __nv_bfloat16 g_flo[(size_t)M_TOK*DFF];

#define O_SAW  0u
#define O_SAOW 4718592u
#define O_FF1  6291456u
#define O_FF2  12582912u
#define O_FC   18874368u
#define WPOOL_E 18940032u
__device__ __nv_bfloat16 g_whi[WPOOL_E];
__device__ __nv_bfloat16 g_wlo[WPOOL_E];

// ---------------------------------------------------------------------------
// Helpers
// ---------------------------------------------------------------------------
__device__ __forceinline__ uint32_t smem_u32(const void* p) {
    uint32_t a;
    asm("{ .reg .u64 t; cvta.to.shared.u64 t, %1; cvt.u32.u64 %0, t; }"
        : "=r"(a) : "l"(p));
    return a;
}
__device__ __forceinline__ void cp_async16(uint32_t dst, const void* src) {
    asm volatile("cp.async.cg.shared.global [%0], [%1], 16;"
                 :: "r"(dst), "l"(src));
}
#define CP_COMMIT() asm volatile("cp.async.commit_group;" ::: "memory")
#define CP_WAIT1()  asm volatile("cp.async.wait_group 1;" ::: "memory")
#define CP_WAIT0()  asm volatile("cp.async.wait_group 0;" ::: "memory")

__device__ __forceinline__ void ldm_x4(uint32_t* r, uint32_t addr) {
    asm volatile("ldmatrix.sync.aligned.m8n8.x4.shared.b16 {%0,%1,%2,%3}, [%4];"
                 : "=r"(r[0]), "=r"(r[1]), "=r"(r[2]), "=r"(r[3]) : "r"(addr));
}
__device__ __forceinline__ void ldm_x4t(uint32_t* r, uint32_t addr) {
    asm volatile("ldmatrix.sync.aligned.m8n8.x4.trans.shared.b16 {%0,%1,%2,%3}, [%4];"
                 : "=r"(r[0]), "=r"(r[1]), "=r"(r[2]), "=r"(r[3]) : "r"(addr));
}
__device__ __forceinline__ void mma_bf16(float* c, const uint32_t* a,
                                         const uint32_t* b) {
    asm volatile(
        "mma.sync.aligned.m16n8k16.row.col.f32.bf16.bf16.f32 "
        "{%0,%1,%2,%3}, {%4,%5,%6,%7}, {%8,%9}, {%0,%1,%2,%3};"
        : "+f"(c[0]), "+f"(c[1]), "+f"(c[2]), "+f"(c[3])
        : "r"(a[0]), "r"(a[1]), "r"(a[2]), "r"(a[3]), "r"(b[0]), "r"(b[1]));
}
__device__ __forceinline__ uint32_t pack2bf(float a, float b) {
    __nv_bfloat162 t = __floats2bfloat162_rn(a, b);
    return *(uint32_t*)&t;
}
__device__ __forceinline__ void split2(float a, float b, uint32_t& hi, uint32_t& lo) {
    __nv_bfloat16 ha = __float2bfloat16_rn(a);
    __nv_bfloat16 hb = __float2bfloat16_rn(b);
    hi = pack2bf(__bfloat162float(ha), __bfloat162float(hb));
    lo = pack2bf(a - __bfloat162float(ha), b - __bfloat162float(hb));
}

// ---------------------------------------------------------------------------
// Embedding: x = emb[tgt]+pos, plus bf16 hi/lo split
// ---------------------------------------------------------------------------
__global__ void embed_kernel(const int* __restrict__ tgt,
                             const float* __restrict__ emb,
                             const float* __restrict__ pos,
                             float* __restrict__ x,
                             __nv_bfloat16* __restrict__ xhi,
                             __nv_bfloat16* __restrict__ xlo) {
    int row = blockIdx.x;
    int d4  = threadIdx.x;             // 128 threads; cols 4*d4..4*d4+3
    int tok = tgt[row];
    int s   = row & (SS - 1);
    float4 e = ((const float4*)(emb + (size_t)tok*DD))[d4];
    float4 p = ((const float4*)(pos + (size_t)s*DD))[d4];
    float4 v = make_float4(e.x+p.x, e.y+p.y, e.z+p.z, e.w+p.w);
    ((float4*)(x + (size_t)row*DD))[d4] = v;
    uint32_t h0, l0, h1, l1;
    split2(v.x, v.y, h0, l0);
    split2(v.z, v.w, h1, l1);
    ((uint2*)(xhi + (size_t)row*DD))[d4] = make_uint2(h0, h1);
    ((uint2*)(xlo + (size_t)row*DD))[d4] = make_uint2(l0, l1);
}

// ---------------------------------------------------------------------------
// fp32 -> bf16 hi/lo (weights only now)
// ---------------------------------------------------------------------------
__global__ void __launch_bounds__(256)
conv_pair(const float* __restrict__ src, __nv_bfloat16* __restrict__ hi,
          __nv_bfloat16* __restrict__ lo) {
    size_t i = (size_t)blockIdx.x * 256 + threadIdx.x;
    float4 v = ((const float4*)src)[i];
    uint32_t h0, l0, h1, l1;
    split2(v.x, v.y, h0, l0);
    split2(v.z, v.w, h1, l1);
    ((uint2*)hi)[i] = make_uint2(h0, h1);
    ((uint2*)lo)[i] = make_uint2(l0, l1);
}

// ---------------------------------------------------------------------------
// HMMA bf16x3 GEMM. mode 0: fp32 C. mode 1: bf16 hi/lo (Chi/Clo), opt ReLU.
// ---------------------------------------------------------------------------
#define HSTAGE 65536
#define HSMEM  (2*HSTAGE)

__global__ void __launch_bounds__(256, 1)
gemm_hmma(const __nv_bfloat16* __restrict__ Ahi,
          const __nv_bfloat16* __restrict__ Alo,
          const __nv_bfloat16* __restrict__ Bhi,
          const __nv_bfloat16* __restrict__ Blo,
          const float* __restrict__ bias, float* __restrict__ C,
          __nv_bfloat16* __restrict__ Chi, __nv_bfloat16* __restrict__ Clo,
          int N, int K, int relu, int mode) {
    extern __shared__ char smg[];
    const uint32_t sa = smem_u32(smg);
    const int tid = threadIdx.x;
    const int wid = tid >> 5, lane = tid & 31;
    const int wM = wid >> 2, wN = wid & 3;
    const int bm = blockIdx.y * 128;
    const int bn = blockIdx.x * 128;
    const int kc = K >> 6;

    float acc[4][4][4];
    #pragma unroll
    for (int i = 0; i < 4; i++)
        #pragma unroll
        for (int j = 0; j < 4; j++)
            #pragma unroll
            for (int e = 0; e < 4; e++) acc[i][j][e] = 0.f;

    auto load_stage = [&](int s, int kk) {
        uint32_t stg = sa + s*HSTAGE;
        #pragma unroll
        for (int i = tid; i < 2048; i += 256) {
            int pool = i >> 10, r = (i >> 3) & 127, c = i & 7;
            const __nv_bfloat16* g =
                (pool ? Alo : Ahi) + (size_t)(bm + r)*K + kk*64 + c*8;
            cp_async16(stg + pool*16384 + r*128 + ((c*16) ^ ((r & 7) << 4)), g);
        }
        #pragma unroll
        for (int i = tid; i < 2048; i += 256) {
            int pool = i >> 10, r = (i >> 3) & 127, c = i & 7;
            const __nv_bfloat16* g =
                (pool ? Blo : Bhi) + (size_t)(bn + r)*K + kk*64 + c*8;
            cp_async16(stg + 32768 + pool*16384 + r*128 +
                       ((c*16) ^ ((r & 7) << 4)), g);
        }
    };

    load_stage(0, 0); CP_COMMIT();
    load_stage(1, 1); CP_COMMIT();

    const int laneA_row = lane & 15;
    const int laneA_b   = (lane >> 4) << 4;
    const int laneB_row = ((lane >> 4) << 3) + (lane & 7);
    const int laneB_b   = ((lane >> 3) & 1) << 4;

    for (int ch = 0; ch < kc; ch++) {
        CP_WAIT1();
        __syncthreads();
        uint32_t stg = sa + (ch & 1)*HSTAGE;

        #pragma unroll
        for (int ks = 0; ks < 4; ks++) {
            uint32_t ah[4][4], al[4][4], bh[2][4], bl[2][4];
            #pragma unroll
            for (int mf = 0; mf < 4; mf++) {
                int r = wM*64 + mf*16 + laneA_row;
                uint32_t off = r*128 + (((uint32_t)(ks*32 + laneA_b)) ^ ((r & 7) << 4));
                ldm_x4(ah[mf], stg + off);
                ldm_x4(al[mf], stg + 16384 + off);
            }
            #pragma unroll
            for (int nf2 = 0; nf2 < 2; nf2++) {
                int r = wN*32 + nf2*16 + laneB_row;
                uint32_t off = r*128 + (((uint32_t)(ks*32 + laneB_b)) ^ ((r & 7) << 4));
                ldm_x4(bh[nf2], stg + 32768 + off);
                ldm_x4(bl[nf2], stg + 49152 + off);
            }
            #pragma unroll
            for (int mf = 0; mf < 4; mf++)
                #pragma unroll
                for (int nf = 0; nf < 4; nf++) {
                    const uint32_t* bhf = &bh[nf >> 1][(nf & 1)*2];
                    const uint32_t* blf = &bl[nf >> 1][(nf & 1)*2];
                    mma_bf16(acc[mf][nf], ah[mf], bhf);
                    mma_bf16(acc[mf][nf], ah[mf], blf);
                    mma_bf16(acc[mf][nf], al[mf], bhf);
                }
        }
        __syncthreads();
        if (ch + 2 < kc) load_stage(ch & 1, ch + 2);
        CP_COMMIT();
    }

    const int gid = lane >> 2, tig = lane & 3;
    #pragma unroll
    for (int mf = 0; mf < 4; mf++) {
        int r0 = bm + wM*64 + mf*16 + gid;
        #pragma unroll
        for (int nf = 0; nf < 4; nf++) {
            int col = bn + wN*32 + nf*8 + tig*2;
            float bx = __ldg(bias + col), by = __ldg(bias + col + 1);
            float v0x = acc[mf][nf][0] + bx, v0y = acc[mf][nf][1] + by;
            float v1x = acc[mf][nf][2] + bx, v1y = acc[mf][nf][3] + by;
            if (relu) {
                v0x = fmaxf(v0x, 0.f); v0y = fmaxf(v0y, 0.f);
                v1x = fmaxf(v1x, 0.f); v1y = fmaxf(v1y, 0.f);
            }
            if (mode == 0) {
                *(float2*)(C + (size_t)r0*N + col)       = make_float2(v0x, v0y);
                *(float2*)(C + (size_t)(r0 + 8)*N + col) = make_float2(v1x, v1y);
            } else {
                uint32_t h, l;
                size_t i0 = (size_t)r0*N + col, i1 = (size_t)(r0 + 8)*N + col;
                split2(v0x, v0y, h, l);
                *(uint32_t*)(Chi + i0) = h; *(uint32_t*)(Clo + i0) = l;
                split2(v1x, v1y, h, l);
                *(uint32_t*)(Chi + i1) = h; *(uint32_t*)(Clo + i1) = l;
            }
        }
    }
}

// ---------------------------------------------------------------------------
// HMMA causal attention. One CTA per (b, h, qb): 64 queries, keys 0..(qb+1)*64.
// qkv hi/lo in [row][1536]. Output written as bf16 hi/lo into ahi/alo [row][512].
// ---------------------------------------------------------------------------
#define OQH 0
#define OQL 8192
#define OKH 16384
#define OKL 49152
#define OVH 81920
#define OVL 114688
#define OPH 147456
#define OPL 180224
#define ORED 212992
#define ATT_SMEM (ORED + 1024)

__global__ void __launch_bounds__(256, 1)
attn_hmma(const __nv_bfloat16* __restrict__ qhi,
          const __nv_bfloat16* __restrict__ qlo,
          __nv_bfloat16* __restrict__ ohi,
          __nv_bfloat16* __restrict__ olo) {
    extern __shared__ char smg[];
    const uint32_t sa = smem_u32(smg);
    const int tid = threadIdx.x;
    const int wid = tid >> 5, lane = tid & 31;
    const int wM = wid >> 1, wN = wid & 1;        // 4 x 2 warps
    const int gid = lane >> 2, tig = lane & 3;

    const int bid = blockIdx.x;
    const int qb = bid & 3;
    const int h  = (bid >> 2) & 7;
    const int b  = bid >> 5;
    const int krows = (qb + 1) * 64;

    // ---- load Q/K/V hi+lo into smem (swizzled 128B rows) ----
    auto load_tile = [&](const __nv_bfloat16* g, uint32_t sbase, int rows) {
        for (int i = tid; i < rows*8; i += 256) {
            int r = i >> 3, c = i & 7;
            cp_async16(sa + sbase + r*128 + ((c*16) ^ ((r & 7) << 4)),
                       g + (size_t)r*1536 + c*8);
        }
    };
    const size_t qbase = (size_t)(b*SS + qb*64)*1536 + h*DH;
    const size_t kbase = (size_t)(b*SS)*1536 + DD + h*DH;
    const size_t vbase = (size_t)(b*SS)*1536 + 2*DD + h*DH;
    load_tile(qhi + qbase, OQH, 64);
    load_tile(qlo + qbase, OQL, 64);
    load_tile(qhi + kbase, OKH, krows);
    load_tile(qlo + kbase, OKL, krows);
    load_tile(qhi + vbase, OVH, krows);
    load_tile(qlo + vbase, OVL, krows);
    CP_COMMIT(); CP_WAIT0();
    __syncthreads();

    const int laneA_row = lane & 15;
    const int laneA_b   = (lane >> 4) << 4;
    const int laneB_row = ((lane >> 4) << 3) + (lane & 7);
    const int laneB_b   = ((lane >> 3) & 1) << 4;

    // ---- QK^T: warp tile 16 x 128, scores fp32 in regs ----
    float s[16][4];
    #pragma unroll
    for (int nt = 0; nt < 16; nt++)
        #pragma unroll
        for (int e = 0; e < 4; e++) s[nt][e] = 0.f;

    #pragma unroll
    for (int ks = 0; ks < 4; ks++) {
        uint32_t ah[4], al[4];
        {
            int r = wM*16 + laneA_row;
            uint32_t off = r*128 + (((uint32_t)(ks*32 + laneA_b)) ^ ((r & 7) << 4));
            ldm_x4(ah, sa + OQH + off);
            ldm_x4(al, sa + OQL + off);
        }
        #pragma unroll
        for (int ng = 0; ng < 8; ng++) {          // 16 keys per group
            uint32_t bh4[4], bl4[4];
            int r = wN*128 + ng*16 + laneB_row;
            uint32_t off = r*128 + (((uint32_t)(ks*32 + laneB_b)) ^ ((r & 7) << 4));
            ldm_x4(bh4, sa + OKH + off);
            ldm_x4(bl4, sa + OKL + off);
            #pragma unroll
            for (int j = 0; j < 2; j++) {
                float* a = s[ng*2 + j];
                mma_bf16(a, ah, &bh4[j*2]);
                mma_bf16(a, ah, &bl4[j*2]);
                mma_bf16(a, al, &bh4[j*2]);
            }
        }
    }

    // ---- mask + softmax ----
    const int qrow0 = qb*64 + wM*16 + gid;   // seq index of row r0
    const int qrow1 = qrow0 + 8;
    float m0 = -1e30f, m1 = -1e30f;
    #pragma unroll
    for (int nt = 0; nt < 16; nt++) {
        int c0 = wN*128 + nt*8 + tig*2;
        s[nt][0] = (c0     <= qrow0) ? s[nt][0]*0.125f : -1e30f;
        s[nt][1] = (c0 + 1 <= qrow0) ? s[nt][1]*0.125f : -1e30f;
        s[nt][2] = (c0     <= qrow1) ? s[nt][2]*0.125f : -1e30f;
        s[nt][3] = (c0 + 1 <= qrow1) ? s[nt][3]*0.125f : -1e30f;
        m0 = fmaxf(m0, fmaxf(s[nt][0], s[nt][1]));
        m1 = fmaxf(m1, fmaxf(s[nt][2], s[nt][3]));
    }
    #pragma unroll
    for (int o = 1; o <= 2; o <<= 1) {
        m0 = fmaxf(m0, __shfl_xor_sync(~0u, m0, o));
        m1 = fmaxf(m1, __shfl_xor_sync(~0u, m1, o));
    }
    float* redm = (float*)(smg + ORED);        // [2][64]
    float* reds = (float*)(smg + ORED + 512);  // [2][64]
    int r0l = wM*16 + gid;
    if (tig == 0) { redm[wN*64 + r0l] = m0; redm[wN*64 + r0l + 8] = m1; }
    __syncthreads();
    m0 = fmaxf(redm[r0l],     redm[64 + r0l]);
    m1 = fmaxf(redm[r0l + 8], redm[64 + r0l + 8]);

    float sum0 = 0.f, sum1 = 0.f;
    #pragma unroll
    for (int nt = 0; nt < 16; nt++) {
        s[nt][0] = __expf(s[nt][0] - m0);
        s[nt][1] = __expf(s[nt][1] - m0);
        s[nt][2] = __expf(s[nt][2] - m1);
        s[nt][3] = __expf(s[nt][3] - m1);
        sum0 += s[nt][0] + s[nt][1];
        sum1 += s[nt][2] + s[nt][3];
    }
    #pragma unroll
    for (int o = 1; o <= 2; o <<= 1) {
        sum0 += __shfl_xor_sync(~0u, sum0, o);
        sum1 += __shfl_xor_sync(~0u, sum1, o);
    }
    if (tig == 0) { reds[wN*64 + r0l] = sum0; reds[wN*64 + r0l + 8] = sum1; }
    __syncthreads();
    float inv0 = 1.f / (reds[r0l]     + reds[64 + r0l]);
    float inv1 = 1.f / (reds[r0l + 8] + reds[64 + r0l + 8]);

    // ---- store P hi/lo (4 blocks of 64 cols, swizzled) ----
    #pragma unroll
    for (int nt = 0; nt < 16; nt++) {
        int c0 = wN*128 + nt*8 + tig*2;
        int kb = c0 >> 6, cb = c0 & 63;
        uint32_t sw0 = (uint32_t)(cb*2) ^ ((r0l & 7) << 4);
        uint32_t sw1 = (uint32_t)(cb*2) ^ (((r0l + 8) & 7) << 4);
        uint32_t off0 = kb*8192 + r0l*128 + sw0;
        uint32_t off1 = kb*8192 + (r0l + 8)*128 + sw1;
        uint32_t h, l;
        split2(s[nt][0]*inv0, s[nt][1]*inv0, h, l);
        *(uint32_t*)(smg + OPH + off0) = h;
        *(uint32_t*)(smg + OPL + off0) = l;
        split2(s[nt][2]*inv1, s[nt][3]*inv1, h, l);
        *(uint32_t*)(smg + OPH + off1) = h;
        *(uint32_t*)(smg + OPL + off1) = l;
    }
    __syncthreads();

    // ---- PV: out 64x64, warp tile 16x32, k over (qb+1)*64 keys ----
    float o[4][4];
    #pragma unroll
    for (int nt = 0; nt < 4; nt++)
        #pragma unroll
        for (int e = 0; e < 4; e++) o[nt][e] = 0.f;

    const int vlrow = lane & 15;
    const uint32_t cbyte0 = (uint32_t)(wN*64 + ((lane >> 4) << 4));
    for (int kb = 0; kb <= qb; kb++) {
        #pragma unroll
        for (int ks = 0; ks < 4; ks++) {
            uint32_t ph4[4], pl4[4];
            {
                int r = wM*16 + laneA_row;
                uint32_t off = kb*8192 + r*128 +
                               (((uint32_t)(ks*32 + laneA_b)) ^ ((r & 7) << 4));
                ldm_x4(ph4, sa + OPH + off);
                ldm_x4(pl4, sa + OPL + off);
            }
            int vr = kb*64 + ks*16 + vlrow;
            #pragma unroll
            for (int chh = 0; chh < 2; chh++) {
                uint32_t vh4[4], vl4[4];
                uint32_t voff = vr*128 + ((cbyte0 + chh*32) ^ ((vr & 7) << 4));
                ldm_x4t(vh4, sa + OVH + voff);
                ldm_x4t(vl4, sa + OVL + voff);
                #pragma unroll
                for (int j = 0; j < 2; j++) {
                    float* a = o[chh*2 + j];
                    mma_bf16(a, ph4, &vh4[j*2]);
                    mma_bf16(a, ph4, &vl4[j*2]);
                    mma_bf16(a, pl4, &vh4[j*2]);
                }
            }
        }
    }

    // ---- write output hi/lo ----
    const int gr0 = b*SS + qb*64 + wM*16 + gid;
    #pragma unroll
    for (int nt = 0; nt < 4; nt++) {
        int col = h*DH + wN*32 + nt*8 + tig*2;
        uint32_t h0, l0, h1, l1;
        split2(o[nt][0], o[nt][1], h0, l0);
        split2(o[nt][2], o[nt][3], h1, l1);
        size_t i0 = (size_t)gr0*DD + col, i1 = (size_t)(gr0 + 8)*DD + col;
        *(uint32_t*)(ohi + i0) = h0; *(uint32_t*)(olo + i0) = l0;
        *(uint32_t*)(ohi + i1) = h1; *(uint32_t*)(olo + i1) = l1;
    }
}

// ---------------------------------------------------------------------------
// fp32 SIMT NT GEMM (tiny cross-attn GEMMs)
// ---------------------------------------------------------------------------
__global__ void __launch_bounds__(256)
gemm_nt(const float* __restrict__ A, const float* __restrict__ B,
        const float* __restrict__ bias, float* __restrict__ C,
        int M, int N, int K, int relu) {
    __shared__ float As[8][128];
    __shared__ float Bs[8][128];
    const int bm = blockIdx.y * 128;
    const int bn = blockIdx.x * 128;
    const int tid = threadIdx.x;
    const int tx = tid & 15, ty = tid >> 4;
    const int lr = tid >> 1, lc = (tid & 1) * 4;
    const int arow = min(bm + lr, M - 1);
    const int brow = bn + lr;

    float acc[8][8];
    #pragma unroll
    for (int i = 0; i < 8; i++)
        #pragma unroll
        for (int j = 0; j < 8; j++) acc[i][j] = 0.f;

    for (int kt = 0; kt < K; kt += 8) {
        {
            float4 v = *(const float4*)(A + (size_t)arow*K + kt + lc);
            As[lc+0][lr] = v.x; As[lc+1][lr] = v.y;
            As[lc+2][lr] = v.z; As[lc+3][lr] = v.w;
        }
        {
            float4 v = *(const float4*)(B + (size_t)brow*K + kt + lc);
            Bs[lc+0][lr] = v.x; Bs[lc+1][lr] = v.y;
            Bs[lc+2][lr] = v.z; Bs[lc+3][lr] = v.w;
        }
        __syncthreads();
        #pragma unroll
        for (int k = 0; k < 8; k++) {
            float a[8], b[8];
            #pragma unroll
            for (int i = 0; i < 8; i++) a[i] = As[k][ty*8 + i];
            #pragma unroll
            for (int j = 0; j < 8; j++) b[j] = Bs[k][tx*8 + j];
            #pragma unroll
            for (int i = 0; i < 8; i++)
                #pragma unroll
                for (int j = 0; j < 8; j++)
                    acc[i][j] = fmaf(a[i], b[j], acc[i][j]);
        }
        __syncthreads();
    }
    #pragma unroll
    for (int i = 0; i < 8; i++) {
        int row = bm + ty*8 + i;
        if (row >= M) continue;
        #pragma unroll
        for (int j = 0; j < 8; j++) {
            int col = bn + tx*8 + j;
            float v = acc[i][j] + bias[col];
            if (relu) v = fmaxf(v, 0.f);
            C[(size_t)row*N + col] = v;
        }
    }
}

// ---------------------------------------------------------------------------
// Fused residual add + LayerNorm + bf16 hi/lo split
// ---------------------------------------------------------------------------
__global__ void __launch_bounds__(128)
add_ln_kernel(float* __restrict__ x, const float* __restrict__ r,
              const float* __restrict__ g, const float* __restrict__ bt,
              int bcast, __nv_bfloat16* __restrict__ xhi,
              __nv_bfloat16* __restrict__ xlo) {
    int row = blockIdx.x;
    const float* rp = r + (bcast ? (size_t)(row >> 8)*DD : (size_t)row*DD);
    float* xp = x + (size_t)row*DD;
    int t = threadIdx.x;

    float4 xv = ((const float4*)xp)[t];
    float4 rv = ((const float4*)rp)[t];
    float v[4] = {xv.x+rv.x, xv.y+rv.y, xv.z+rv.z, xv.w+rv.w};
    float sum = v[0] + v[1] + v[2] + v[3];

    __shared__ float red1[4], red2[4];
    #pragma unroll
    for (int o = 16; o; o >>= 1) sum += __shfl_xor_sync(~0u, sum, o);
    if ((t & 31) == 0) red1[t >> 5] = sum;
    __syncthreads();
    float mean = (red1[0] + red1[1] + red1[2] + red1[3]) * (1.f/512.f);

    float var = 0.f;
    #pragma unroll
    for (int i = 0; i < 4; i++) {
        float d = v[i] - mean;
        var = fmaf(d, d, var);
    }
    #pragma unroll
    for (int o = 16; o; o >>= 1) var += __shfl_xor_sync(~0u, var, o);
    if ((t & 31) == 0) red2[t >> 5] = var;
    __syncthreads();
    float rs = rsqrtf((red2[0] + red2[1] + red2[2] + red2[3]) * (1.f/512.f) + 1e-5f);

    float4 gv = ((const float4*)(g  + 0))[t];
    float4 bv = ((const float4*)(bt + 0))[t];
    float o0 = (v[0] - mean) * rs * gv.x + bv.x;
    float o1 = (v[1] - mean) * rs * gv.y + bv.y;
    float o2 = (v[2] - mean) * rs * gv.z + bv.z;
    float o3 = (v[3] - mean) * rs * gv.w + bv.w;
    ((float4*)xp)[t] = make_float4(o0, o1, o2, o3);
    uint32_t h0, l0, h1, l1;
    split2(o0, o1, h0, l0);
    split2(o2, o3, h1, l1);
    ((uint2*)(xhi + (size_t)row*DD))[t] = make_uint2(h0, h1);
    ((uint2*)(xlo + (size_t)row*DD))[t] = make_uint2(l0, l1);
}

// ---------------------------------------------------------------------------
// Launch
// ---------------------------------------------------------------------------
extern "C" void kernel_launch(void* const* d_in, const int* in_sizes, int n_in,
                              void* d_out, int out_size) {
    const float* z      = (const float*)d_in[0];
    const int*   tgt    = (const int*)  d_in[1];
    const float* emb    = (const float*)d_in[2];
    const float* pos    = (const float*)d_in[3];
    const float* proj_w = (const float*)d_in[4];
    const float* proj_b = (const float*)d_in[5];
    const float* sa_w   = (const float*)d_in[6];
    const float* sa_b   = (const float*)d_in[7];
    const float* sa_ow  = (const float*)d_in[8];
    const float* sa_ob  = (const float*)d_in[9];
    const float* ca_w   = (const float*)d_in[10];
    const float* ca_b   = (const float*)d_in[11];
    const float* ca_ow  = (const float*)d_in[12];
    const float* ca_ob  = (const float*)d_in[13];
    const float* ln1_s  = (const float*)d_in[14];
    const float* ln1_b  = (const float*)d_in[15];
    const float* ln2_s  = (const float*)d_in[16];
    const float* ln2_b  = (const float*)d_in[17];
    const float* ln3_s  = (const float*)d_in[18];
    const float* ln3_b  = (const float*)d_in[19];
    const float* ff1_w  = (const float*)d_in[20];
    const float* ff1_b  = (const float*)d_in[21];
    const float* ff2_w  = (const float*)d_in[22];
    const float* ff2_b  = (const float*)d_in[23];
    const float* fc_w   = (const float*)d_in[24];
    const float* fc_b   = (const float*)d_in[25];
    float* out = (float*)d_out;

    float *x, *sub, *mem, *cav, *ca;
    __nv_bfloat16 *ahi, *alo, *qhi, *qlo, *fhi, *flo, *whi, *wlo;
    cudaGetSymbolAddress((void**)&x,   g_x);
    cudaGetSymbolAddress((void**)&sub, g_sub);
    cudaGetSymbolAddress((void**)&mem, g_mem);
    cudaGetSymbolAddress((void**)&cav, g_cav);
    cudaGetSymbolAddress((void**)&ca,  g_ca);
    cudaGetSymbolAddress((void**)&ahi, g_ahi);
    cudaGetSymbolAddress((void**)&alo, g_alo);
    cudaGetSymbolAddress((void**)&qhi, g_qhi);
    cudaGetSymbolAddress((void**)&qlo, g_qlo);
    cudaGetSymbolAddress((void**)&fhi, g_fhi);
    cudaGetSymbolAddress((void**)&flo, g_flo);
    cudaGetSymbolAddress((void**)&whi, g_whi);
    cudaGetSymbolAddress((void**)&wlo, g_wlo);

    cudaFuncSetAttribute(gemm_hmma,
                         cudaFuncAttributeMaxDynamicSharedMemorySize, HSMEM);
    cudaFuncSetAttribute(attn_hmma,
                         cudaFuncAttributeMaxDynamicSharedMemorySize, ATT_SMEM);

    // ---- weight conversion ----
    conv_pair<<<6*3*DD*DD/1024, 256>>>(sa_w,  whi + O_SAW,  wlo + O_SAW);
    conv_pair<<<6*DD*DD/1024,   256>>>(sa_ow, whi + O_SAOW, wlo + O_SAOW);
    conv_pair<<<6*DFF*DD/1024,  256>>>(ff1_w, whi + O_FF1,  wlo + O_FF1);
    conv_pair<<<6*DD*DFF/1024,  256>>>(ff2_w, whi + O_FF2,  wlo + O_FF2);
    conv_pair<<<VV*DD/1024,     256>>>(fc_w,  whi + O_FC,   wlo + O_FC);

    // ---- embedding + memory projection ----
    embed_kernel<<<M_TOK, 128>>>(tgt, emb, pos, x, ahi, alo);
    gemm_nt<<<dim3(DD/128, 1), 256>>>(z, proj_w, proj_b, mem, BB, DD, DD, 0);

    for (int l = 0; l < LL; l++) {
        const float* sabl  = sa_b  + (size_t)l*3*DD;
        const float* saobl = sa_ob + (size_t)l*DD;
        const float* cawv  = ca_w  + (size_t)l*3*DD*DD + (size_t)2*DD*DD;
        const float* cabv  = ca_b  + (size_t)l*3*DD + 2*DD;
        const float* caowl = ca_ow + (size_t)l*DD*DD;
        const float* caobl = ca_ob + (size_t)l*DD;
        size_t o_qkv = O_SAW  + (size_t)l*3*DD*DD;
        size_t o_ow  = O_SAOW + (size_t)l*DD*DD;
        size_t o_ff1 = O_FF1  + (size_t)l*DFF*DD;
        size_t o_ff2 = O_FF2  + (size_t)l*DD*DFF;

        // self-attention
        gemm_hmma<<<dim3(12, 128), 256, HSMEM>>>(ahi, alo, whi + o_qkv,
                                                 wlo + o_qkv, sabl, nullptr,
                                                 qhi, qlo, 3*DD, DD, 0, 1);
        attn_hmma<<<BB*HH*4, 256, ATT_SMEM>>>(qhi, qlo, ahi, alo);
        gemm_hmma<<<dim3(4, 128), 256, HSMEM>>>(ahi, alo, whi + o_ow,
                                                wlo + o_ow, saobl, sub,
                                                nullptr, nullptr, DD, DD, 0, 0);
        add_ln_kernel<<<M_TOK, 128>>>(x, sub, ln1_s + l*DD, ln1_b + l*DD, 0,
                                      ahi, alo);

        // cross-attention (length-1 memory)
        gemm_nt<<<dim3(DD/128, 1), 256>>>(mem, cawv, cabv, cav, BB, DD, DD, 0);
        gemm_nt<<<dim3(DD/128, 1), 256>>>(cav, caowl, caobl, ca, BB, DD, DD, 0);
        add_ln_kernel<<<M_TOK, 128>>>(x, ca, ln2_s + l*DD, ln2_b + l*DD, 1,
                                      ahi, alo);

        // feed-forward
        gemm_hmma<<<dim3(16, 128), 256, HSMEM>>>(ahi, alo, whi + o_ff1,
                                                 wlo + o_ff1, ff1_b + l*DFF,
                                                 nullptr, fhi, flo,
                                                 DFF, DD, 1, 1);
        gemm_hmma<<<dim3(4, 128), 256, HSMEM>>>(fhi, flo, whi + o_ff2,
                                                wlo + o_ff2, ff2_b + l*DD,
                                                sub, nullptr, nullptr,
                                                DD, DFF, 0, 0);
        add_ln_kernel<<<M_TOK, 128>>>(x, sub, ln3_s + l*DD, ln3_b + l*DD, 0,
                                      ahi, alo);
    }

    // final classifier
    gemm_hmma<<<dim3(1, 128), 256, HSMEM>>>(ahi, alo, whi + O_FC, wlo + O_FC,
                                            fc_b, out, nullptr, nullptr,
                                            VV, DD, 0, 0);
}

// round 6
// speedup vs baseline: 3.5191x; 1.1717x over previous
#include <cuda_runtime.h>
#include <cuda_bf16.h>
#include <math.h>
#include <stdint.h>

#define BB 64
#define SS 256
#define DD 512
#define HH 8
#define DH 64
#define DFF 2048
#define VV 128
#define LL 6
#define M_TOK (BB*SS)

// ---------------------------------------------------------------------------
// Scratch
// ---------------------------------------------------------------------------
__device__ float g_x  [M_TOK*DD];
__device__ float g_sub[M_TOK*DD];
__device__ float g_mem[BB*DD];
__device__ float g_cav[LL*BB*DD];
__device__ float g_ca [LL*BB*DD];

// activation bf16 hi/lo pools
__device__ __nv_bfloat16 g_ahi[(size_t)M_TOK*DD];
__device__ __nv_bfloat16 g_alo[(size_t)M_TOK*DD];
__device__ __nv_bfloat16 g_qhi[(size_t)M_TOK*3*DD];
__device__ __nv_bfloat16 g_qlo[(size_t)M_TOK*3*DD];
__device__ __nv_bfloat16 g_fhi[(size_t)M_TOK*DFF];
__device__ __nv_bfloat16 g_flo[(size_t)M_TOK*DFF];

#define O_SAW  0u
#define O_SAOW 4718592u
#define O_FF1  6291456u
#define O_FF2  12582912u
#define O_FC   18874368u
#define WPOOL_E 18940032u
__device__ __nv_bfloat16 g_whi[WPOOL_E];
__device__ __nv_bfloat16 g_wlo[WPOOL_E];

// ---------------------------------------------------------------------------
// Helpers
// ---------------------------------------------------------------------------
__device__ __forceinline__ uint32_t smem_u32(const void* p) {
    uint32_t a;
    asm("{ .reg .u64 t; cvta.to.shared.u64 t, %1; cvt.u32.u64 %0, t; }"
        : "=r"(a) : "l"(p));
    return a;
}
__device__ __forceinline__ void cp_async16(uint32_t dst, const void* src) {
    asm volatile("cp.async.cg.shared.global [%0], [%1], 16;"
                 :: "r"(dst), "l"(src));
}
#define CP_COMMIT() asm volatile("cp.async.commit_group;" ::: "memory")
#define CP_WAIT2()  asm volatile("cp.async.wait_group 2;" ::: "memory")
#define CP_WAIT0()  asm volatile("cp.async.wait_group 0;" ::: "memory")

__device__ __forceinline__ void ldm_x4(uint32_t* r, uint32_t addr) {
    asm volatile("ldmatrix.sync.aligned.m8n8.x4.shared.b16 {%0,%1,%2,%3}, [%4];"
                 : "=r"(r[0]), "=r"(r[1]), "=r"(r[2]), "=r"(r[3]) : "r"(addr));
}
__device__ __forceinline__ void ldm_x4t(uint32_t* r, uint32_t addr) {
    asm volatile("ldmatrix.sync.aligned.m8n8.x4.trans.shared.b16 {%0,%1,%2,%3}, [%4];"
                 : "=r"(r[0]), "=r"(r[1]), "=r"(r[2]), "=r"(r[3]) : "r"(addr));
}
__device__ __forceinline__ void mma_bf16(float* c, const uint32_t* a,
                                         const uint32_t* b) {
    asm volatile(
        "mma.sync.aligned.m16n8k16.row.col.f32.bf16.bf16.f32 "
        "{%0,%1,%2,%3}, {%4,%5,%6,%7}, {%8,%9}, {%0,%1,%2,%3};"
        : "+f"(c[0]), "+f"(c[1]), "+f"(c[2]), "+f"(c[3])
        : "r"(a[0]), "r"(a[1]), "r"(a[2]), "r"(a[3]), "r"(b[0]), "r"(b[1]));
}
__device__ __forceinline__ uint32_t pack2bf(float a, float b) {
    __nv_bfloat162 t = __floats2bfloat162_rn(a, b);
    return *(uint32_t*)&t;
}
__device__ __forceinline__ void split2(float a, float b, uint32_t& hi, uint32_t& lo) {
    __nv_bfloat16 ha = __float2bfloat16_rn(a);
    __nv_bfloat16 hb = __float2bfloat16_rn(b);
    hi = pack2bf(__bfloat162float(ha), __bfloat162float(hb));
    lo = pack2bf(a - __bfloat162float(ha), b - __bfloat162float(hb));
}

// ---------------------------------------------------------------------------
// Embedding
// ---------------------------------------------------------------------------
__global__ void embed_kernel(const int* __restrict__ tgt,
                             const float* __restrict__ emb,
                             const float* __restrict__ pos,
                             float* __restrict__ x,
                             __nv_bfloat16* __restrict__ xhi,
                             __nv_bfloat16* __restrict__ xlo) {
    int row = blockIdx.x;
    int d4  = threadIdx.x;
    int tok = tgt[row];
    int s   = row & (SS - 1);
    float4 e = ((const float4*)(emb + (size_t)tok*DD))[d4];
    float4 p = ((const float4*)(pos + (size_t)s*DD))[d4];
    float4 v = make_float4(e.x+p.x, e.y+p.y, e.z+p.z, e.w+p.w);
    ((float4*)(x + (size_t)row*DD))[d4] = v;
    uint32_t h0, l0, h1, l1;
    split2(v.x, v.y, h0, l0);
    split2(v.z, v.w, h1, l1);
    ((uint2*)(xhi + (size_t)row*DD))[d4] = make_uint2(h0, h1);
    ((uint2*)(xlo + (size_t)row*DD))[d4] = make_uint2(l0, l1);
}

// ---------------------------------------------------------------------------
// fp32 -> bf16 hi/lo (weights)
// ---------------------------------------------------------------------------
__global__ void __launch_bounds__(256)
conv_pair(const float* __restrict__ src, __nv_bfloat16* __restrict__ hi,
          __nv_bfloat16* __restrict__ lo) {
    size_t i = (size_t)blockIdx.x * 256 + threadIdx.x;
    float4 v = ((const float4*)src)[i];
    uint32_t h0, l0, h1, l1;
    split2(v.x, v.y, h0, l0);
    split2(v.z, v.w, h1, l1);
    ((uint2*)hi)[i] = make_uint2(h0, h1);
    ((uint2*)lo)[i] = make_uint2(l0, l1);
}

// ---------------------------------------------------------------------------
// HMMA bf16x3 GEMM, 3-stage cp.async pipeline.
// mode 0: fp32 C.  mode 1: bf16 hi/lo out (Chi/Clo), opt ReLU.
// ---------------------------------------------------------------------------
#define HSTAGE 65536
#define HSMEM  (3*HSTAGE)

__global__ void __launch_bounds__(256, 1)
gemm_hmma(const __nv_bfloat16* __restrict__ Ahi,
          const __nv_bfloat16* __restrict__ Alo,
          const __nv_bfloat16* __restrict__ Bhi,
          const __nv_bfloat16* __restrict__ Blo,
          const float* __restrict__ bias, float* __restrict__ C,
          __nv_bfloat16* __restrict__ Chi, __nv_bfloat16* __restrict__ Clo,
          int N, int K, int relu, int mode) {
    extern __shared__ char smg[];
    const uint32_t sa = smem_u32(smg);
    const int tid = threadIdx.x;
    const int wid = tid >> 5, lane = tid & 31;
    const int wM = wid >> 2, wN = wid & 3;
    const int bm = blockIdx.y * 128;
    const int bn = blockIdx.x * 128;
    const int kc = K >> 6;

    float acc[4][4][4];
    #pragma unroll
    for (int i = 0; i < 4; i++)
        #pragma unroll
        for (int j = 0; j < 4; j++)
            #pragma unroll
            for (int e = 0; e < 4; e++) acc[i][j][e] = 0.f;

    auto load_stage = [&](int s, int kk) {
        uint32_t stg = sa + s*HSTAGE;
        #pragma unroll
        for (int i = tid; i < 2048; i += 256) {
            int pool = i >> 10, r = (i >> 3) & 127, c = i & 7;
            const __nv_bfloat16* g =
                (pool ? Alo : Ahi) + (size_t)(bm + r)*K + kk*64 + c*8;
            cp_async16(stg + pool*16384 + r*128 + ((c*16) ^ ((r & 7) << 4)), g);
        }
        #pragma unroll
        for (int i = tid; i < 2048; i += 256) {
            int pool = i >> 10, r = (i >> 3) & 127, c = i & 7;
            const __nv_bfloat16* g =
                (pool ? Blo : Bhi) + (size_t)(bn + r)*K + kk*64 + c*8;
            cp_async16(stg + 32768 + pool*16384 + r*128 +
                       ((c*16) ^ ((r & 7) << 4)), g);
        }
    };

    // prologue: fill 3 stages (kc >= 8 always)
    load_stage(0, 0); CP_COMMIT();
    load_stage(1, 1); CP_COMMIT();
    load_stage(2, 2); CP_COMMIT();

    const int laneA_row = lane & 15;
    const int laneA_b   = (lane >> 4) << 4;
    const int laneB_row = ((lane >> 4) << 3) + (lane & 7);
    const int laneB_b   = ((lane >> 3) & 1) << 4;

    int sidx = 0;
    for (int ch = 0; ch < kc; ch++) {
        CP_WAIT2();
        __syncthreads();
        uint32_t stg = sa + sidx*HSTAGE;

        #pragma unroll
        for (int ks = 0; ks < 4; ks++) {
            uint32_t ah[4][4], al[4][4], bh[2][4], bl[2][4];
            #pragma unroll
            for (int mf = 0; mf < 4; mf++) {
                int r = wM*64 + mf*16 + laneA_row;
                uint32_t off = r*128 + (((uint32_t)(ks*32 + laneA_b)) ^ ((r & 7) << 4));
                ldm_x4(ah[mf], stg + off);
                ldm_x4(al[mf], stg + 16384 + off);
            }
            #pragma unroll
            for (int nf2 = 0; nf2 < 2; nf2++) {
                int r = wN*32 + nf2*16 + laneB_row;
                uint32_t off = r*128 + (((uint32_t)(ks*32 + laneB_b)) ^ ((r & 7) << 4));
                ldm_x4(bh[nf2], stg + 32768 + off);
                ldm_x4(bl[nf2], stg + 49152 + off);
            }
            #pragma unroll
            for (int mf = 0; mf < 4; mf++)
                #pragma unroll
                for (int nf = 0; nf < 4; nf++) {
                    const uint32_t* bhf = &bh[nf >> 1][(nf & 1)*2];
                    const uint32_t* blf = &bl[nf >> 1][(nf & 1)*2];
                    mma_bf16(acc[mf][nf], ah[mf], bhf);
                    mma_bf16(acc[mf][nf], ah[mf], blf);
                    mma_bf16(acc[mf][nf], al[mf], bhf);
                }
        }
        __syncthreads();
        if (ch + 3 < kc) load_stage(sidx, ch + 3);
        CP_COMMIT();
        sidx = (sidx == 2) ? 0 : sidx + 1;
    }

    const int gid = lane >> 2, tig = lane & 3;
    #pragma unroll
    for (int mf = 0; mf < 4; mf++) {
        int r0 = bm + wM*64 + mf*16 + gid;
        #pragma unroll
        for (int nf = 0; nf < 4; nf++) {
            int col = bn + wN*32 + nf*8 + tig*2;
            float bx = __ldg(bias + col), by = __ldg(bias + col + 1);
            float v0x = acc[mf][nf][0] + bx, v0y = acc[mf][nf][1] + by;
            float v1x = acc[mf][nf][2] + bx, v1y = acc[mf][nf][3] + by;
            if (relu) {
                v0x = fmaxf(v0x, 0.f); v0y = fmaxf(v0y, 0.f);
                v1x = fmaxf(v1x, 0.f); v1y = fmaxf(v1y, 0.f);
            }
            if (mode == 0) {
                *(float2*)(C + (size_t)r0*N + col)       = make_float2(v0x, v0y);
                *(float2*)(C + (size_t)(r0 + 8)*N + col) = make_float2(v1x, v1y);
            } else {
                uint32_t h, l;
                size_t i0 = (size_t)r0*N + col, i1 = (size_t)(r0 + 8)*N + col;
                split2(v0x, v0y, h, l);
                *(uint32_t*)(Chi + i0) = h; *(uint32_t*)(Clo + i0) = l;
                split2(v1x, v1y, h, l);
                *(uint32_t*)(Chi + i1) = h; *(uint32_t*)(Clo + i1) = l;
            }
        }
    }
}

// ---------------------------------------------------------------------------
// HMMA causal attention (unchanged from R5 passing version)
// ---------------------------------------------------------------------------
#define OQH 0
#define OQL 8192
#define OKH 16384
#define OKL 49152
#define OVH 81920
#define OVL 114688
#define OPH 147456
#define OPL 180224
#define ORED 212992
#define ATT_SMEM (ORED + 1024)

__global__ void __launch_bounds__(256, 1)
attn_hmma(const __nv_bfloat16* __restrict__ qhi,
          const __nv_bfloat16* __restrict__ qlo,
          __nv_bfloat16* __restrict__ ohi,
          __nv_bfloat16* __restrict__ olo) {
    extern __shared__ char smg[];
    const uint32_t sa = smem_u32(smg);
    const int tid = threadIdx.x;
    const int wid = tid >> 5, lane = tid & 31;
    const int wM = wid >> 1, wN = wid & 1;
    const int gid = lane >> 2, tig = lane & 3;

    const int bid = blockIdx.x;
    const int qb = bid & 3;
    const int h  = (bid >> 2) & 7;
    const int b  = bid >> 5;
    const int krows = (qb + 1) * 64;

    auto load_tile = [&](const __nv_bfloat16* g, uint32_t sbase, int rows) {
        for (int i = tid; i < rows*8; i += 256) {
            int r = i >> 3, c = i & 7;
            cp_async16(sa + sbase + r*128 + ((c*16) ^ ((r & 7) << 4)),
                       g + (size_t)r*1536 + c*8);
        }
    };
    const size_t qbase = (size_t)(b*SS + qb*64)*1536 + h*DH;
    const size_t kbase = (size_t)(b*SS)*1536 + DD + h*DH;
    const size_t vbase = (size_t)(b*SS)*1536 + 2*DD + h*DH;
    load_tile(qhi + qbase, OQH, 64);
    load_tile(qlo + qbase, OQL, 64);
    load_tile(qhi + kbase, OKH, krows);
    load_tile(qlo + kbase, OKL, krows);
    load_tile(qhi + vbase, OVH, krows);
    load_tile(qlo + vbase, OVL, krows);
    CP_COMMIT(); CP_WAIT0();
    __syncthreads();

    const int laneA_row = lane & 15;
    const int laneA_b   = (lane >> 4) << 4;
    const int laneB_row = ((lane >> 4) << 3) + (lane & 7);
    const int laneB_b   = ((lane >> 3) & 1) << 4;

    float s[16][4];
    #pragma unroll
    for (int nt = 0; nt < 16; nt++)
        #pragma unroll
        for (int e = 0; e < 4; e++) s[nt][e] = 0.f;

    #pragma unroll
    for (int ks = 0; ks < 4; ks++) {
        uint32_t ah[4], al[4];
        {
            int r = wM*16 + laneA_row;
            uint32_t off = r*128 + (((uint32_t)(ks*32 + laneA_b)) ^ ((r & 7) << 4));
            ldm_x4(ah, sa + OQH + off);
            ldm_x4(al, sa + OQL + off);
        }
        #pragma unroll
        for (int ng = 0; ng < 8; ng++) {
            uint32_t bh4[4], bl4[4];
            int r = wN*128 + ng*16 + laneB_row;
            uint32_t off = r*128 + (((uint32_t)(ks*32 + laneB_b)) ^ ((r & 7) << 4));
            ldm_x4(bh4, sa + OKH + off);
            ldm_x4(bl4, sa + OKL + off);
            #pragma unroll
            for (int j = 0; j < 2; j++) {
                float* a = s[ng*2 + j];
                mma_bf16(a, ah, &bh4[j*2]);
                mma_bf16(a, ah, &bl4[j*2]);
                mma_bf16(a, al, &bh4[j*2]);
            }
        }
    }

    const int qrow0 = qb*64 + wM*16 + gid;
    const int qrow1 = qrow0 + 8;
    float m0 = -1e30f, m1 = -1e30f;
    #pragma unroll
    for (int nt = 0; nt < 16; nt++) {
        int c0 = wN*128 + nt*8 + tig*2;
        s[nt][0] = (c0     <= qrow0) ? s[nt][0]*0.125f : -1e30f;
        s[nt][1] = (c0 + 1 <= qrow0) ? s[nt][1]*0.125f : -1e30f;
        s[nt][2] = (c0     <= qrow1) ? s[nt][2]*0.125f : -1e30f;
        s[nt][3] = (c0 + 1 <= qrow1) ? s[nt][3]*0.125f : -1e30f;
        m0 = fmaxf(m0, fmaxf(s[nt][0], s[nt][1]));
        m1 = fmaxf(m1, fmaxf(s[nt][2], s[nt][3]));
    }
    #pragma unroll
    for (int o = 1; o <= 2; o <<= 1) {
        m0 = fmaxf(m0, __shfl_xor_sync(~0u, m0, o));
        m1 = fmaxf(m1, __shfl_xor_sync(~0u, m1, o));
    }
    float* redm = (float*)(smg + ORED);
    float* reds = (float*)(smg + ORED + 512);
    int r0l = wM*16 + gid;
    if (tig == 0) { redm[wN*64 + r0l] = m0; redm[wN*64 + r0l + 8] = m1; }
    __syncthreads();
    m0 = fmaxf(redm[r0l],     redm[64 + r0l]);
    m1 = fmaxf(redm[r0l + 8], redm[64 + r0l + 8]);

    float sum0 = 0.f, sum1 = 0.f;
    #pragma unroll
    for (int nt = 0; nt < 16; nt++) {
        s[nt][0] = __expf(s[nt][0] - m0);
        s[nt][1] = __expf(s[nt][1] - m0);
        s[nt][2] = __expf(s[nt][2] - m1);
        s[nt][3] = __expf(s[nt][3] - m1);
        sum0 += s[nt][0] + s[nt][1];
        sum1 += s[nt][2] + s[nt][3];
    }
    #pragma unroll
    for (int o = 1; o <= 2; o <<= 1) {
        sum0 += __shfl_xor_sync(~0u, sum0, o);
        sum1 += __shfl_xor_sync(~0u, sum1, o);
    }
    if (tig == 0) { reds[wN*64 + r0l] = sum0; reds[wN*64 + r0l + 8] = sum1; }
    __syncthreads();
    float inv0 = 1.f / (reds[r0l]     + reds[64 + r0l]);
    float inv1 = 1.f / (reds[r0l + 8] + reds[64 + r0l + 8]);

    #pragma unroll
    for (int nt = 0; nt < 16; nt++) {
        int c0 = wN*128 + nt*8 + tig*2;
        int kb = c0 >> 6, cb = c0 & 63;
        uint32_t sw0 = (uint32_t)(cb*2) ^ ((r0l & 7) << 4);
        uint32_t sw1 = (uint32_t)(cb*2) ^ (((r0l + 8) & 7) << 4);
        uint32_t off0 = kb*8192 + r0l*128 + sw0;
        uint32_t off1 = kb*8192 + (r0l + 8)*128 + sw1;
        uint32_t h, l;
        split2(s[nt][0]*inv0, s[nt][1]*inv0, h, l);
        *(uint32_t*)(smg + OPH + off0) = h;
        *(uint32_t*)(smg + OPL + off0) = l;
        split2(s[nt][2]*inv1, s[nt][3]*inv1, h, l);
        *(uint32_t*)(smg + OPH + off1) = h;
        *(uint32_t*)(smg + OPL + off1) = l;
    }
    __syncthreads();

    float o[4][4];
    #pragma unroll
    for (int nt = 0; nt < 4; nt++)
        #pragma unroll
        for (int e = 0; e < 4; e++) o[nt][e] = 0.f;

    const int vlrow = lane & 15;
    const uint32_t cbyte0 = (uint32_t)(wN*64 + ((lane >> 4) << 4));
    for (int kb = 0; kb <= qb; kb++) {
        #pragma unroll
        for (int ks = 0; ks < 4; ks++) {
            uint32_t ph4[4], pl4[4];
            {
                int r = wM*16 + laneA_row;
                uint32_t off = kb*8192 + r*128 +
                               (((uint32_t)(ks*32 + laneA_b)) ^ ((r & 7) << 4));
                ldm_x4(ph4, sa + OPH + off);
                ldm_x4(pl4, sa + OPL + off);
            }
            int vr = kb*64 + ks*16 + vlrow;
            #pragma unroll
            for (int chh = 0; chh < 2; chh++) {
                uint32_t vh4[4], vl4[4];
                uint32_t voff = vr*128 + ((cbyte0 + chh*32) ^ ((vr & 7) << 4));
                ldm_x4t(vh4, sa + OVH + voff);
                ldm_x4t(vl4, sa + OVL + voff);
                #pragma unroll
                for (int j = 0; j < 2; j++) {
                    float* a = o[chh*2 + j];
                    mma_bf16(a, ph4, &vh4[j*2]);
                    mma_bf16(a, ph4, &vl4[j*2]);
                    mma_bf16(a, pl4, &vh4[j*2]);
                }
            }
        }
    }

    const int gr0 = b*SS + qb*64 + wM*16 + gid;
    #pragma unroll
    for (int nt = 0; nt < 4; nt++) {
        int col = h*DH + wN*32 + nt*8 + tig*2;
        uint32_t h0, l0, h1, l1;
        split2(o[nt][0], o[nt][1], h0, l0);
        split2(o[nt][2], o[nt][3], h1, l1);
        size_t i0 = (size_t)gr0*DD + col, i1 = (size_t)(gr0 + 8)*DD + col;
        *(uint32_t*)(ohi + i0) = h0; *(uint32_t*)(olo + i0) = l0;
        *(uint32_t*)(ohi + i1) = h1; *(uint32_t*)(olo + i1) = l1;
    }
}

// ---------------------------------------------------------------------------
// fp32 SIMT NT GEMM, z-batched (cross-attn per-layer micro-GEMMs + mem proj)
// ---------------------------------------------------------------------------
__global__ void __launch_bounds__(256)
gemm_nt_b(const float* __restrict__ A, size_t astr,
          const float* __restrict__ B, size_t bstr,
          const float* __restrict__ bias, size_t bistr,
          float* __restrict__ C, size_t cstr,
          int M, int N, int K) {
    const int zz = blockIdx.z;
    A += zz*astr; B += zz*bstr; bias += zz*bistr; C += zz*cstr;

    __shared__ float As[8][128];
    __shared__ float Bs[8][128];
    const int bm = blockIdx.y * 128;
    const int bn = blockIdx.x * 128;
    const int tid = threadIdx.x;
    const int tx = tid & 15, ty = tid >> 4;
    const int lr = tid >> 1, lc = (tid & 1) * 4;
    const int arow = min(bm + lr, M - 1);
    const int brow = bn + lr;

    float acc[8][8];
    #pragma unroll
    for (int i = 0; i < 8; i++)
        #pragma unroll
        for (int j = 0; j < 8; j++) acc[i][j] = 0.f;

    for (int kt = 0; kt < K; kt += 8) {
        {
            float4 v = *(const float4*)(A + (size_t)arow*K + kt + lc);
            As[lc+0][lr] = v.x; As[lc+1][lr] = v.y;
            As[lc+2][lr] = v.z; As[lc+3][lr] = v.w;
        }
        {
            float4 v = *(const float4*)(B + (size_t)brow*K + kt + lc);
            Bs[lc+0][lr] = v.x; Bs[lc+1][lr] = v.y;
            Bs[lc+2][lr] = v.z; Bs[lc+3][lr] = v.w;
        }
        __syncthreads();
        #pragma unroll
        for (int k = 0; k < 8; k++) {
            float a[8], b[8];
            #pragma unroll
            for (int i = 0; i < 8; i++) a[i] = As[k][ty*8 + i];
            #pragma unroll
            for (int j = 0; j < 8; j++) b[j] = Bs[k][tx*8 + j];
            #pragma unroll
            for (int i = 0; i < 8; i++)
                #pragma unroll
                for (int j = 0; j < 8; j++)
                    acc[i][j] = fmaf(a[i], b[j], acc[i][j]);
        }
        __syncthreads();
    }
    #pragma unroll
    for (int i = 0; i < 8; i++) {
        int row = bm + ty*8 + i;
        if (row >= M) continue;
        #pragma unroll
        for (int j = 0; j < 8; j++) {
            int col = bn + tx*8 + j;
            C[(size_t)row*N + col] = acc[i][j] + bias[col];
        }
    }
}

// ---------------------------------------------------------------------------
// Fused residual add + LayerNorm + bf16 hi/lo split
// ---------------------------------------------------------------------------
__global__ void __launch_bounds__(128)
add_ln_kernel(float* __restrict__ x, const float* __restrict__ r,
              const float* __restrict__ g, const float* __restrict__ bt,
              int bcast, __nv_bfloat16* __restrict__ xhi,
              __nv_bfloat16* __restrict__ xlo) {
    int row = blockIdx.x;
    const float* rp = r + (bcast ? (size_t)(row >> 8)*DD : (size_t)row*DD);
    float* xp = x + (size_t)row*DD;
    int t = threadIdx.x;

    float4 xv = ((const float4*)xp)[t];
    float4 rv = ((const float4*)rp)[t];
    float v[4] = {xv.x+rv.x, xv.y+rv.y, xv.z+rv.z, xv.w+rv.w};
    float sum = v[0] + v[1] + v[2] + v[3];

    __shared__ float red1[4], red2[4];
    #pragma unroll
    for (int o = 16; o; o >>= 1) sum += __shfl_xor_sync(~0u, sum, o);
    if ((t & 31) == 0) red1[t >> 5] = sum;
    __syncthreads();
    float mean = (red1[0] + red1[1] + red1[2] + red1[3]) * (1.f/512.f);

    float var = 0.f;
    #pragma unroll
    for (int i = 0; i < 4; i++) {
        float d = v[i] - mean;
        var = fmaf(d, d, var);
    }
    #pragma unroll
    for (int o = 16; o; o >>= 1) var += __shfl_xor_sync(~0u, var, o);
    if ((t & 31) == 0) red2[t >> 5] = var;
    __syncthreads();
    float rs = rsqrtf((red2[0] + red2[1] + red2[2] + red2[3]) * (1.f/512.f) + 1e-5f);

    float4 gv = ((const float4*)g)[t];
    float4 bv = ((const float4*)bt)[t];
    float o0 = (v[0] - mean) * rs * gv.x + bv.x;
    float o1 = (v[1] - mean) * rs * gv.y + bv.y;
    float o2 = (v[2] - mean) * rs * gv.z + bv.z;
    float o3 = (v[3] - mean) * rs * gv.w + bv.w;
    ((float4*)xp)[t] = make_float4(o0, o1, o2, o3);
    uint32_t h0, l0, h1, l1;
    split2(o0, o1, h0, l0);
    split2(o2, o3, h1, l1);
    ((uint2*)(xhi + (size_t)row*DD))[t] = make_uint2(h0, h1);
    ((uint2*)(xlo + (size_t)row*DD))[t] = make_uint2(l0, l1);
}

// ---------------------------------------------------------------------------
// Launch
// ---------------------------------------------------------------------------
extern "C" void kernel_launch(void* const* d_in, const int* in_sizes, int n_in,
                              void* d_out, int out_size) {
    const float* z      = (const float*)d_in[0];
    const int*   tgt    = (const int*)  d_in[1];
    const float* emb    = (const float*)d_in[2];
    const float* pos    = (const float*)d_in[3];
    const float* proj_w = (const float*)d_in[4];
    const float* proj_b = (const float*)d_in[5];
    const float* sa_w   = (const float*)d_in[6];
    const float* sa_b   = (const float*)d_in[7];
    const float* sa_ow  = (const float*)d_in[8];
    const float* sa_ob  = (const float*)d_in[9];
    const float* ca_w   = (const float*)d_in[10];
    const float* ca_b   = (const float*)d_in[11];
    const float* ca_ow  = (const float*)d_in[12];
    const float* ca_ob  = (const float*)d_in[13];
    const float* ln1_s  = (const float*)d_in[14];
    const float* ln1_b  = (const float*)d_in[15];
    const float* ln2_s  = (const float*)d_in[16];
    const float* ln2_b  = (const float*)d_in[17];
    const float* ln3_s  = (const float*)d_in[18];
    const float* ln3_b  = (const float*)d_in[19];
    const float* ff1_w  = (const float*)d_in[20];
    const float* ff1_b  = (const float*)d_in[21];
    const float* ff2_w  = (const float*)d_in[22];
    const float* ff2_b  = (const float*)d_in[23];
    const float* fc_w   = (const float*)d_in[24];
    const float* fc_b   = (const float*)d_in[25];
    float* out = (float*)d_out;

    float *x, *sub, *mem, *cav, *ca;
    __nv_bfloat16 *ahi, *alo, *qhi, *qlo, *fhi, *flo, *whi, *wlo;
    cudaGetSymbolAddress((void**)&x,   g_x);
    cudaGetSymbolAddress((void**)&sub, g_sub);
    cudaGetSymbolAddress((void**)&mem, g_mem);
    cudaGetSymbolAddress((void**)&cav, g_cav);
    cudaGetSymbolAddress((void**)&ca,  g_ca);
    cudaGetSymbolAddress((void**)&ahi, g_ahi);
    cudaGetSymbolAddress((void**)&alo, g_alo);
    cudaGetSymbolAddress((void**)&qhi, g_qhi);
    cudaGetSymbolAddress((void**)&qlo, g_qlo);
    cudaGetSymbolAddress((void**)&fhi, g_fhi);
    cudaGetSymbolAddress((void**)&flo, g_flo);
    cudaGetSymbolAddress((void**)&whi, g_whi);
    cudaGetSymbolAddress((void**)&wlo, g_wlo);

    cudaFuncSetAttribute(gemm_hmma,
                         cudaFuncAttributeMaxDynamicSharedMemorySize, HSMEM);
    cudaFuncSetAttribute(attn_hmma,
                         cudaFuncAttributeMaxDynamicSharedMemorySize, ATT_SMEM);

    // ---- weight conversion ----
    conv_pair<<<6*3*DD*DD/1024, 256>>>(sa_w,  whi + O_SAW,  wlo + O_SAW);
    conv_pair<<<6*DD*DD/1024,   256>>>(sa_ow, whi + O_SAOW, wlo + O_SAOW);
    conv_pair<<<6*DFF*DD/1024,  256>>>(ff1_w, whi + O_FF1,  wlo + O_FF1);
    conv_pair<<<6*DD*DFF/1024,  256>>>(ff2_w, whi + O_FF2,  wlo + O_FF2);
    conv_pair<<<VV*DD/1024,     256>>>(fc_w,  whi + O_FC,   wlo + O_FC);

    // ---- embedding + memory projection ----
    embed_kernel<<<M_TOK, 128>>>(tgt, emb, pos, x, ahi, alo);
    gemm_nt_b<<<dim3(DD/128, 1, 1), 256>>>(z, 0, proj_w, 0, proj_b, 0,
                                           mem, 0, BB, DD, DD);

    // ---- batched cross-attention vectors for all layers ----
    // cav[l] = mem @ Wv_l^T + bv_l ; ca[l] = cav[l] @ Wo_l^T + ob_l
    gemm_nt_b<<<dim3(DD/128, 1, LL), 256>>>(
        mem, 0,
        ca_w + (size_t)2*DD*DD, (size_t)3*DD*DD,
        ca_b + 2*DD, (size_t)3*DD,
        cav, (size_t)BB*DD, BB, DD, DD);
    gemm_nt_b<<<dim3(DD/128, 1, LL), 256>>>(
        cav, (size_t)BB*DD,
        ca_ow, (size_t)DD*DD,
        ca_ob, (size_t)DD,
        ca, (size_t)BB*DD, BB, DD, DD);

    for (int l = 0; l < LL; l++) {
        const float* sabl  = sa_b  + (size_t)l*3*DD;
        const float* saobl = sa_ob + (size_t)l*DD;
        size_t o_qkv = O_SAW  + (size_t)l*3*DD*DD;
        size_t o_ow  = O_SAOW + (size_t)l*DD*DD;
        size_t o_ff1 = O_FF1  + (size_t)l*DFF*DD;
        size_t o_ff2 = O_FF2  + (size_t)l*DD*DFF;

        // self-attention
        gemm_hmma<<<dim3(12, 128), 256, HSMEM>>>(ahi, alo, whi + o_qkv,
                                                 wlo + o_qkv, sabl, nullptr,
                                                 qhi, qlo, 3*DD, DD, 0, 1);
        attn_hmma<<<BB*HH*4, 256, ATT_SMEM>>>(qhi, qlo, ahi, alo);
        gemm_hmma<<<dim3(4, 128), 256, HSMEM>>>(ahi, alo, whi + o_ow,
                                                wlo + o_ow, saobl, sub,
                                                nullptr, nullptr, DD, DD, 0, 0);
        add_ln_kernel<<<M_TOK, 128>>>(x, sub, ln1_s + l*DD, ln1_b + l*DD, 0,
                                      ahi, alo);

        // cross-attention residual (precomputed per-batch vector)
        add_ln_kernel<<<M_TOK, 128>>>(x, ca + (size_t)l*BB*DD,
                                      ln2_s + l*DD, ln2_b + l*DD, 1, ahi, alo);

        // feed-forward
        gemm_hmma<<<dim3(16, 128), 256, HSMEM>>>(ahi, alo, whi + o_ff1,
                                                 wlo + o_ff1, ff1_b + l*DFF,
                                                 nullptr, fhi, flo,
                                                 DFF, DD, 1, 1);
        gemm_hmma<<<dim3(4, 128), 256, HSMEM>>>(fhi, flo, whi + o_ff2,
                                                wlo + o_ff2, ff2_b + l*DD,
                                                sub, nullptr, nullptr,
                                                DD, DFF, 0, 0);
        add_ln_kernel<<<M_TOK, 128>>>(x, sub, ln3_s + l*DD, ln3_b + l*DD, 0,
                                      ahi, alo);
    }

    // final classifier
    gemm_hmma<<<dim3(1, 128), 256, HSMEM>>>(ahi, alo, whi + O_FC, wlo + O_FC,
                                            fc_b, out, nullptr, nullptr,
                                            VV, DD, 0, 0);
}

// round 7
// speedup vs baseline: 3.5434x; 1.0069x over previous
#include <cuda_runtime.h>
#include <cuda_bf16.h>
#include <math.h>
#include <stdint.h>

#define BB 64
#define SS 256
#define DD 512
#define HH 8
#define DH 64
#define DFF 2048
#define VV 128
#define LL 6
#define M_TOK (BB*SS)

// ---------------------------------------------------------------------------
// Scratch
// ---------------------------------------------------------------------------
__device__ float g_x  [M_TOK*DD];
__device__ float g_sub[M_TOK*DD];
__device__ float g_mem[BB*DD];
__device__ float g_cav[LL*BB*DD];
__device__ float g_ca [LL*BB*DD];

__device__ __nv_bfloat16 g_ahi[(size_t)M_TOK*DD];
__device__ __nv_bfloat16 g_alo[(size_t)M_TOK*DD];
__device__ __nv_bfloat16 g_qhi[(size_t)M_TOK*3*DD];
__device__ __nv_bfloat16 g_qlo[(size_t)M_TOK*3*DD];
__device__ __nv_bfloat16 g_fhi[(size_t)M_TOK*DFF];
__device__ __nv_bfloat16 g_flo[(size_t)M_TOK*DFF];

#define O_SAW  0u
#define O_SAOW 4718592u
#define O_FF1  6291456u
#define O_FF2  12582912u
#define O_FC   18874368u
#define WPOOL_E 18940032u
__device__ __nv_bfloat16 g_whi[WPOOL_E];
__device__ __nv_bfloat16 g_wlo[WPOOL_E];

// ---------------------------------------------------------------------------
// Helpers
// ---------------------------------------------------------------------------
__device__ __forceinline__ uint32_t smem_u32(const void* p) {
    uint32_t a;
    asm("{ .reg .u64 t; cvta.to.shared.u64 t, %1; cvt.u32.u64 %0, t; }"
        : "=r"(a) : "l"(p));
    return a;
}
__device__ __forceinline__ void cp_async16(uint32_t dst, const void* src) {
    asm volatile("cp.async.cg.shared.global [%0], [%1], 16;"
                 :: "r"(dst), "l"(src));
}
#define CP_COMMIT() asm volatile("cp.async.commit_group;" ::: "memory")
#define CP_WAIT1()  asm volatile("cp.async.wait_group 1;" ::: "memory")
#define CP_WAIT0()  asm volatile("cp.async.wait_group 0;" ::: "memory")

__device__ __forceinline__ void ldm_x4(uint32_t* r, uint32_t addr) {
    asm volatile("ldmatrix.sync.aligned.m8n8.x4.shared.b16 {%0,%1,%2,%3}, [%4];"
                 : "=r"(r[0]), "=r"(r[1]), "=r"(r[2]), "=r"(r[3]) : "r"(addr));
}
__device__ __forceinline__ void ldm_x4t(uint32_t* r, uint32_t addr) {
    asm volatile("ldmatrix.sync.aligned.m8n8.x4.trans.shared.b16 {%0,%1,%2,%3}, [%4];"
                 : "=r"(r[0]), "=r"(r[1]), "=r"(r[2]), "=r"(r[3]) : "r"(addr));
}
__device__ __forceinline__ void mma_bf16(float* c, const uint32_t* a,
                                         const uint32_t* b) {
    asm volatile(
        "mma.sync.aligned.m16n8k16.row.col.f32.bf16.bf16.f32 "
        "{%0,%1,%2,%3}, {%4,%5,%6,%7}, {%8,%9}, {%0,%1,%2,%3};"
        : "+f"(c[0]), "+f"(c[1]), "+f"(c[2]), "+f"(c[3])
        : "r"(a[0]), "r"(a[1]), "r"(a[2]), "r"(a[3]), "r"(b[0]), "r"(b[1]));
}
__device__ __forceinline__ uint32_t pack2bf(float a, float b) {
    __nv_bfloat162 t = __floats2bfloat162_rn(a, b);
    return *(uint32_t*)&t;
}
__device__ __forceinline__ void split2(float a, float b, uint32_t& hi, uint32_t& lo) {
    __nv_bfloat16 ha = __float2bfloat16_rn(a);
    __nv_bfloat16 hb = __float2bfloat16_rn(b);
    hi = pack2bf(__bfloat162float(ha), __bfloat162float(hb));
    lo = pack2bf(a - __bfloat162float(ha), b - __bfloat162float(hb));
}

// ---------------------------------------------------------------------------
// Embedding
// ---------------------------------------------------------------------------
__global__ void embed_kernel(const int* __restrict__ tgt,
                             const float* __restrict__ emb,
                             const float* __restrict__ pos,
                             float* __restrict__ x,
                             __nv_bfloat16* __restrict__ xhi,
                             __nv_bfloat16* __restrict__ xlo) {
    int row = blockIdx.x;
    int d4  = threadIdx.x;
    int tok = tgt[row];
    int s   = row & (SS - 1);
    float4 e = ((const float4*)(emb + (size_t)tok*DD))[d4];
    float4 p = ((const float4*)(pos + (size_t)s*DD))[d4];
    float4 v = make_float4(e.x+p.x, e.y+p.y, e.z+p.z, e.w+p.w);
    ((float4*)(x + (size_t)row*DD))[d4] = v;
    uint32_t h0, l0, h1, l1;
    split2(v.x, v.y, h0, l0);
    split2(v.z, v.w, h1, l1);
    ((uint2*)(xhi + (size_t)row*DD))[d4] = make_uint2(h0, h1);
    ((uint2*)(xlo + (size_t)row*DD))[d4] = make_uint2(l0, l1);
}

// ---------------------------------------------------------------------------
// fp32 -> bf16 hi/lo (weights)
// ---------------------------------------------------------------------------
__global__ void __launch_bounds__(256)
conv_pair(const float* __restrict__ src, __nv_bfloat16* __restrict__ hi,
          __nv_bfloat16* __restrict__ lo) {
    size_t i = (size_t)blockIdx.x * 256 + threadIdx.x;
    float4 v = ((const float4*)src)[i];
    uint32_t h0, l0, h1, l1;
    split2(v.x, v.y, h0, l0);
    split2(v.z, v.w, h1, l1);
    ((uint2*)hi)[i] = make_uint2(h0, h1);
    ((uint2*)lo)[i] = make_uint2(l0, l1);
}

// ---------------------------------------------------------------------------
// HMMA bf16x3 GEMM, 256(M)x128(N) CTA tile, 2-stage cp.async pipeline.
// 8 warps 4x2, warp tile 64x64. mode 0: fp32 C. mode 1: bf16 hi/lo + opt ReLU.
// Stage: Ahi 32K | Alo 32K | Bhi 16K | Blo 16K = 96 KB.
// ---------------------------------------------------------------------------
#define G2STAGE 98304
#define G2SMEM  (2*G2STAGE)

__global__ void __launch_bounds__(256, 1)
gemm_hmma2(const __nv_bfloat16* __restrict__ Ahi,
           const __nv_bfloat16* __restrict__ Alo,
           const __nv_bfloat16* __restrict__ Bhi,
           const __nv_bfloat16* __restrict__ Blo,
           const float* __restrict__ bias, float* __restrict__ C,
           __nv_bfloat16* __restrict__ Chi, __nv_bfloat16* __restrict__ Clo,
           int N, int K, int relu, int mode) {
    extern __shared__ char smg[];
    const uint32_t sa = smem_u32(smg);
    const int tid = threadIdx.x;
    const int wid = tid >> 5, lane = tid & 31;
    const int wM = wid >> 1, wN = wid & 1;       // 4 x 2 warps
    const int bm = blockIdx.y * 256;
    const int bn = blockIdx.x * 128;
    const int kc = K >> 6;

    float acc[4][8][4];
    #pragma unroll
    for (int i = 0; i < 4; i++)
        #pragma unroll
        for (int j = 0; j < 8; j++)
            #pragma unroll
            for (int e = 0; e < 4; e++) acc[i][j][e] = 0.f;

    auto load_stage = [&](int s, int kk) {
        uint32_t stg = sa + s*G2STAGE;
        #pragma unroll
        for (int i = tid; i < 4096; i += 256) {   // A hi+lo: 256 rows x 8 cgrp
            int pool = i >> 11, r = (i >> 3) & 255, c = i & 7;
            const __nv_bfloat16* g =
                (pool ? Alo : Ahi) + (size_t)(bm + r)*K + kk*64 + c*8;
            cp_async16(stg + pool*32768 + r*128 + ((c*16) ^ ((r & 7) << 4)), g);
        }
        #pragma unroll
        for (int i = tid; i < 2048; i += 256) {   // B hi+lo: 128 rows
            int pool = i >> 10, r = (i >> 3) & 127, c = i & 7;
            const __nv_bfloat16* g =
                (pool ? Blo : Bhi) + (size_t)(bn + r)*K + kk*64 + c*8;
            cp_async16(stg + 65536 + pool*16384 + r*128 +
                       ((c*16) ^ ((r & 7) << 4)), g);
        }
    };

    load_stage(0, 0); CP_COMMIT();
    load_stage(1, 1); CP_COMMIT();

    const int laneA_row = lane & 15;
    const int laneA_b   = (lane >> 4) << 4;
    const int laneB_row = ((lane >> 4) << 3) + (lane & 7);
    const int laneB_b   = ((lane >> 3) & 1) << 4;

    for (int ch = 0; ch < kc; ch++) {
        CP_WAIT1();
        __syncthreads();
        uint32_t stg = sa + (ch & 1)*G2STAGE;

        #pragma unroll
        for (int ks = 0; ks < 4; ks++) {
            uint32_t ah[4][4], al[4][4];
            #pragma unroll
            for (int mf = 0; mf < 4; mf++) {
                int r = wM*64 + mf*16 + laneA_row;
                uint32_t off = r*128 + (((uint32_t)(ks*32 + laneA_b)) ^ ((r & 7) << 4));
                ldm_x4(ah[mf], stg + off);
                ldm_x4(al[mf], stg + 32768 + off);
            }
            #pragma unroll
            for (int nf2 = 0; nf2 < 4; nf2++) {
                uint32_t bh4[4], bl4[4];
                int r = wN*64 + nf2*16 + laneB_row;
                uint32_t off = r*128 + (((uint32_t)(ks*32 + laneB_b)) ^ ((r & 7) << 4));
                ldm_x4(bh4, stg + 65536 + off);
                ldm_x4(bl4, stg + 81920 + off);
                #pragma unroll
                for (int mf = 0; mf < 4; mf++)
                    #pragma unroll
                    for (int j = 0; j < 2; j++) {
                        float* a = acc[mf][nf2*2 + j];
                        mma_bf16(a, ah[mf], &bh4[j*2]);
                        mma_bf16(a, ah[mf], &bl4[j*2]);
                        mma_bf16(a, al[mf], &bh4[j*2]);
                    }
            }
        }
        __syncthreads();
        if (ch + 2 < kc) load_stage(ch & 1, ch + 2);
        CP_COMMIT();
    }

    const int gid = lane >> 2, tig = lane & 3;
    #pragma unroll
    for (int mf = 0; mf < 4; mf++) {
        int r0 = bm + wM*64 + mf*16 + gid;
        #pragma unroll
        for (int nf = 0; nf < 8; nf++) {
            int col = bn + wN*64 + nf*8 + tig*2;
            float bx = __ldg(bias + col), by = __ldg(bias + col + 1);
            float v0x = acc[mf][nf][0] + bx, v0y = acc[mf][nf][1] + by;
            float v1x = acc[mf][nf][2] + bx, v1y = acc[mf][nf][3] + by;
            if (relu) {
                v0x = fmaxf(v0x, 0.f); v0y = fmaxf(v0y, 0.f);
                v1x = fmaxf(v1x, 0.f); v1y = fmaxf(v1y, 0.f);
            }
            if (mode == 0) {
                *(float2*)(C + (size_t)r0*N + col)       = make_float2(v0x, v0y);
                *(float2*)(C + (size_t)(r0 + 8)*N + col) = make_float2(v1x, v1y);
            } else {
                uint32_t h, l;
                size_t i0 = (size_t)r0*N + col, i1 = (size_t)(r0 + 8)*N + col;
                split2(v0x, v0y, h, l);
                *(uint32_t*)(Chi + i0) = h; *(uint32_t*)(Clo + i0) = l;
                split2(v1x, v1y, h, l);
                *(uint32_t*)(Chi + i1) = h; *(uint32_t*)(Clo + i1) = l;
            }
        }
    }
}

// ---------------------------------------------------------------------------
// HMMA causal attention (split cp.async groups: QK first, V deferred)
// ---------------------------------------------------------------------------
#define OQH 0
#define OQL 8192
#define OKH 16384
#define OKL 49152
#define OVH 81920
#define OVL 114688
#define OPH 147456
#define OPL 180224
#define ORED 212992
#define ATT_SMEM (ORED + 1024)

__global__ void __launch_bounds__(256, 1)
attn_hmma(const __nv_bfloat16* __restrict__ qhi,
          const __nv_bfloat16* __restrict__ qlo,
          __nv_bfloat16* __restrict__ ohi,
          __nv_bfloat16* __restrict__ olo) {
    extern __shared__ char smg[];
    const uint32_t sa = smem_u32(smg);
    const int tid = threadIdx.x;
    const int wid = tid >> 5, lane = tid & 31;
    const int wM = wid >> 1, wN = wid & 1;
    const int gid = lane >> 2, tig = lane & 3;

    const int bid = blockIdx.x;
    const int qb = bid & 3;
    const int h  = (bid >> 2) & 7;
    const int b  = bid >> 5;
    const int krows = (qb + 1) * 64;

    auto load_tile = [&](const __nv_bfloat16* g, uint32_t sbase, int rows) {
        for (int i = tid; i < rows*8; i += 256) {
            int r = i >> 3, c = i & 7;
            cp_async16(sa + sbase + r*128 + ((c*16) ^ ((r & 7) << 4)),
                       g + (size_t)r*1536 + c*8);
        }
    };
    const size_t qbase = (size_t)(b*SS + qb*64)*1536 + h*DH;
    const size_t kbase = (size_t)(b*SS)*1536 + DD + h*DH;
    const size_t vbase = (size_t)(b*SS)*1536 + 2*DD + h*DH;
    load_tile(qhi + qbase, OQH, 64);
    load_tile(qlo + qbase, OQL, 64);
    load_tile(qhi + kbase, OKH, krows);
    load_tile(qlo + kbase, OKL, krows);
    CP_COMMIT();
    load_tile(qhi + vbase, OVH, krows);
    load_tile(qlo + vbase, OVL, krows);
    CP_COMMIT();
    CP_WAIT1();                 // Q,K ready; V may still be in flight
    __syncthreads();

    const int laneA_row = lane & 15;
    const int laneA_b   = (lane >> 4) << 4;
    const int laneB_row = ((lane >> 4) << 3) + (lane & 7);
    const int laneB_b   = ((lane >> 3) & 1) << 4;

    float s[16][4];
    #pragma unroll
    for (int nt = 0; nt < 16; nt++)
        #pragma unroll
        for (int e = 0; e < 4; e++) s[nt][e] = 0.f;

    #pragma unroll
    for (int ks = 0; ks < 4; ks++) {
        uint32_t ah[4], al[4];
        {
            int r = wM*16 + laneA_row;
            uint32_t off = r*128 + (((uint32_t)(ks*32 + laneA_b)) ^ ((r & 7) << 4));
            ldm_x4(ah, sa + OQH + off);
            ldm_x4(al, sa + OQL + off);
        }
        #pragma unroll
        for (int ng = 0; ng < 8; ng++) {
            uint32_t bh4[4], bl4[4];
            int r = wN*128 + ng*16 + laneB_row;
            uint32_t off = r*128 + (((uint32_t)(ks*32 + laneB_b)) ^ ((r & 7) << 4));
            ldm_x4(bh4, sa + OKH + off);
            ldm_x4(bl4, sa + OKL + off);
            #pragma unroll
            for (int j = 0; j < 2; j++) {
                float* a = s[ng*2 + j];
                mma_bf16(a, ah, &bh4[j*2]);
                mma_bf16(a, ah, &bl4[j*2]);
                mma_bf16(a, al, &bh4[j*2]);
            }
        }
    }

    const int qrow0 = qb*64 + wM*16 + gid;
    const int qrow1 = qrow0 + 8;
    float m0 = -1e30f, m1 = -1e30f;
    #pragma unroll
    for (int nt = 0; nt < 16; nt++) {
        int c0 = wN*128 + nt*8 + tig*2;
        s[nt][0] = (c0     <= qrow0) ? s[nt][0]*0.125f : -1e30f;
        s[nt][1] = (c0 + 1 <= qrow0) ? s[nt][1]*0.125f : -1e30f;
        s[nt][2] = (c0     <= qrow1) ? s[nt][2]*0.125f : -1e30f;
        s[nt][3] = (c0 + 1 <= qrow1) ? s[nt][3]*0.125f : -1e30f;
        m0 = fmaxf(m0, fmaxf(s[nt][0], s[nt][1]));
        m1 = fmaxf(m1, fmaxf(s[nt][2], s[nt][3]));
    }
    #pragma unroll
    for (int o = 1; o <= 2; o <<= 1) {
        m0 = fmaxf(m0, __shfl_xor_sync(~0u, m0, o));
        m1 = fmaxf(m1, __shfl_xor_sync(~0u, m1, o));
    }
    float* redm = (float*)(smg + ORED);
    float* reds = (float*)(smg + ORED + 512);
    int r0l = wM*16 + gid;
    if (tig == 0) { redm[wN*64 + r0l] = m0; redm[wN*64 + r0l + 8] = m1; }
    __syncthreads();
    m0 = fmaxf(redm[r0l],     redm[64 + r0l]);
    m1 = fmaxf(redm[r0l + 8], redm[64 + r0l + 8]);

    float sum0 = 0.f, sum1 = 0.f;
    #pragma unroll
    for (int nt = 0; nt < 16; nt++) {
        s[nt][0] = __expf(s[nt][0] - m0);
        s[nt][1] = __expf(s[nt][1] - m0);
        s[nt][2] = __expf(s[nt][2] - m1);
        s[nt][3] = __expf(s[nt][3] - m1);
        sum0 += s[nt][0] + s[nt][1];
        sum1 += s[nt][2] + s[nt][3];
    }
    #pragma unroll
    for (int o = 1; o <= 2; o <<= 1) {
        sum0 += __shfl_xor_sync(~0u, sum0, o);
        sum1 += __shfl_xor_sync(~0u, sum1, o);
    }
    if (tig == 0) { reds[wN*64 + r0l] = sum0; reds[wN*64 + r0l + 8] = sum1; }
    __syncthreads();
    float inv0 = 1.f / (reds[r0l]     + reds[64 + r0l]);
    float inv1 = 1.f / (reds[r0l + 8] + reds[64 + r0l + 8]);

    #pragma unroll
    for (int nt = 0; nt < 16; nt++) {
        int c0 = wN*128 + nt*8 + tig*2;
        int kb = c0 >> 6, cb = c0 & 63;
        uint32_t sw0 = (uint32_t)(cb*2) ^ ((r0l & 7) << 4);
        uint32_t sw1 = (uint32_t)(cb*2) ^ (((r0l + 8) & 7) << 4);
        uint32_t off0 = kb*8192 + r0l*128 + sw0;
        uint32_t off1 = kb*8192 + (r0l + 8)*128 + sw1;
        uint32_t h, l;
        split2(s[nt][0]*inv0, s[nt][1]*inv0, h, l);
        *(uint32_t*)(smg + OPH + off0) = h;
        *(uint32_t*)(smg + OPL + off0) = l;
        split2(s[nt][2]*inv1, s[nt][3]*inv1, h, l);
        *(uint32_t*)(smg + OPH + off1) = h;
        *(uint32_t*)(smg + OPL + off1) = l;
    }
    CP_WAIT0();                 // V resident
    __syncthreads();

    float o[4][4];
    #pragma unroll
    for (int nt = 0; nt < 4; nt++)
        #pragma unroll
        for (int e = 0; e < 4; e++) o[nt][e] = 0.f;

    const int vlrow = lane & 15;
    const uint32_t cbyte0 = (uint32_t)(wN*64 + ((lane >> 4) << 4));
    for (int kb = 0; kb <= qb; kb++) {
        #pragma unroll
        for (int ks = 0; ks < 4; ks++) {
            uint32_t ph4[4], pl4[4];
            {
                int r = wM*16 + laneA_row;
                uint32_t off = kb*8192 + r*128 +
                               (((uint32_t)(ks*32 + laneA_b)) ^ ((r & 7) << 4));
                ldm_x4(ph4, sa + OPH + off);
                ldm_x4(pl4, sa + OPL + off);
            }
            int vr = kb*64 + ks*16 + vlrow;
            #pragma unroll
            for (int chh = 0; chh < 2; chh++) {
                uint32_t vh4[4], vl4[4];
                uint32_t voff = vr*128 + ((cbyte0 + chh*32) ^ ((vr & 7) << 4));
                ldm_x4t(vh4, sa + OVH + voff);
                ldm_x4t(vl4, sa + OVL + voff);
                #pragma unroll
                for (int j = 0; j < 2; j++) {
                    float* a = o[chh*2 + j];
                    mma_bf16(a, ph4, &vh4[j*2]);
                    mma_bf16(a, ph4, &vl4[j*2]);
                    mma_bf16(a, pl4, &vh4[j*2]);
                }
            }
        }
    }

    const int gr0 = b*SS + qb*64 + wM*16 + gid;
    #pragma unroll
    for (int nt = 0; nt < 4; nt++) {
        int col = h*DH + wN*32 + nt*8 + tig*2;
        uint32_t h0, l0, h1, l1;
        split2(o[nt][0], o[nt][1], h0, l0);
        split2(o[nt][2], o[nt][3], h1, l1);
        size_t i0 = (size_t)gr0*DD + col, i1 = (size_t)(gr0 + 8)*DD + col;
        *(uint32_t*)(ohi + i0) = h0; *(uint32_t*)(olo + i0) = l0;
        *(uint32_t*)(ohi + i1) = h1; *(uint32_t*)(olo + i1) = l1;
    }
}

// ---------------------------------------------------------------------------
// fp32 SIMT NT GEMM, z-batched
// ---------------------------------------------------------------------------
__global__ void __launch_bounds__(256)
gemm_nt_b(const float* __restrict__ A, size_t astr,
          const float* __restrict__ B, size_t bstr,
          const float* __restrict__ bias, size_t bistr,
          float* __restrict__ C, size_t cstr,
          int M, int N, int K) {
    const int zz = blockIdx.z;
    A += zz*astr; B += zz*bstr; bias += zz*bistr; C += zz*cstr;

    __shared__ float As[8][128];
    __shared__ float Bs[8][128];
    const int bm = blockIdx.y * 128;
    const int bn = blockIdx.x * 128;
    const int tid = threadIdx.x;
    const int tx = tid & 15, ty = tid >> 4;
    const int lr = tid >> 1, lc = (tid & 1) * 4;
    const int arow = min(bm + lr, M - 1);
    const int brow = bn + lr;

    float acc[8][8];
    #pragma unroll
    for (int i = 0; i < 8; i++)
        #pragma unroll
        for (int j = 0; j < 8; j++) acc[i][j] = 0.f;

    for (int kt = 0; kt < K; kt += 8) {
        {
            float4 v = *(const float4*)(A + (size_t)arow*K + kt + lc);
            As[lc+0][lr] = v.x; As[lc+1][lr] = v.y;
            As[lc+2][lr] = v.z; As[lc+3][lr] = v.w;
        }
        {
            float4 v = *(const float4*)(B + (size_t)brow*K + kt + lc);
            Bs[lc+0][lr] = v.x; Bs[lc+1][lr] = v.y;
            Bs[lc+2][lr] = v.z; Bs[lc+3][lr] = v.w;
        }
        __syncthreads();
        #pragma unroll
        for (int k = 0; k < 8; k++) {
            float a[8], b[8];
            #pragma unroll
            for (int i = 0; i < 8; i++) a[i] = As[k][ty*8 + i];
            #pragma unroll
            for (int j = 0; j < 8; j++) b[j] = Bs[k][tx*8 + j];
            #pragma unroll
            for (int i = 0; i < 8; i++)
                #pragma unroll
                for (int j = 0; j < 8; j++)
                    acc[i][j] = fmaf(a[i], b[j], acc[i][j]);
        }
        __syncthreads();
    }
    #pragma unroll
    for (int i = 0; i < 8; i++) {
        int row = bm + ty*8 + i;
        if (row >= M) continue;
        #pragma unroll
        for (int j = 0; j < 8; j++) {
            int col = bn + tx*8 + j;
            C[(size_t)row*N + col] = acc[i][j] + bias[col];
        }
    }
}

// ---------------------------------------------------------------------------
// LN body (device helper): y = LN(v)*g + b, via block reduce (128 thr, 4/thread)
// ---------------------------------------------------------------------------
__device__ __forceinline__ void ln_block(float* v, const float4 gv,
                                         const float4 bv, int t,
                                         float* red, float* o) {
    float sum = v[0] + v[1] + v[2] + v[3];
    #pragma unroll
    for (int oo = 16; oo; oo >>= 1) sum += __shfl_xor_sync(~0u, sum, oo);
    if ((t & 31) == 0) red[t >> 5] = sum;
    __syncthreads();
    float mean = (red[0] + red[1] + red[2] + red[3]) * (1.f/512.f);
    float var = 0.f;
    #pragma unroll
    for (int i = 0; i < 4; i++) {
        float d = v[i] - mean;
        var = fmaf(d, d, var);
    }
    #pragma unroll
    for (int oo = 16; oo; oo >>= 1) var += __shfl_xor_sync(~0u, var, oo);
    if ((t & 31) == 0) red[4 + (t >> 5)] = var;
    __syncthreads();
    float rs = rsqrtf((red[4] + red[5] + red[6] + red[7]) * (1.f/512.f) + 1e-5f);
    o[0] = (v[0] - mean) * rs * gv.x + bv.x;
    o[1] = (v[1] - mean) * rs * gv.y + bv.y;
    o[2] = (v[2] - mean) * rs * gv.z + bv.z;
    o[3] = (v[3] - mean) * rs * gv.w + bv.w;
}

// ---------------------------------------------------------------------------
// Single add+LN (+hi/lo split)
// ---------------------------------------------------------------------------
__global__ void __launch_bounds__(128)
add_ln_kernel(float* __restrict__ x, const float* __restrict__ r,
              const float* __restrict__ g, const float* __restrict__ bt,
              __nv_bfloat16* __restrict__ xhi, __nv_bfloat16* __restrict__ xlo) {
    int row = blockIdx.x;
    const float* rp = r + (size_t)row*DD;
    float* xp = x + (size_t)row*DD;
    int t = threadIdx.x;
    __shared__ float red[8];

    float4 xv = ((const float4*)xp)[t];
    float4 rv = ((const float4*)rp)[t];
    float v[4] = {xv.x+rv.x, xv.y+rv.y, xv.z+rv.z, xv.w+rv.w};
    float o[4];
    ln_block(v, ((const float4*)g)[t], ((const float4*)bt)[t], t, red, o);
    ((float4*)xp)[t] = make_float4(o[0], o[1], o[2], o[3]);
    uint32_t h0, l0, h1, l1;
    split2(o[0], o[1], h0, l0);
    split2(o[2], o[3], h1, l1);
    ((uint2*)(xhi + (size_t)row*DD))[t] = make_uint2(h0, h1);
    ((uint2*)(xlo + (size_t)row*DD))[t] = make_uint2(l0, l1);
}

// ---------------------------------------------------------------------------
// Fused double LN: x = LN2( LN1(x + sub) + ca[b] ), + hi/lo split
// ---------------------------------------------------------------------------
__global__ void __launch_bounds__(128)
add_ln2_kernel(float* __restrict__ x, const float* __restrict__ sub,
               const float* __restrict__ ca,
               const float* __restrict__ g1, const float* __restrict__ b1,
               const float* __restrict__ g2, const float* __restrict__ b2,
               __nv_bfloat16* __restrict__ xhi, __nv_bfloat16* __restrict__ xlo) {
    int row = blockIdx.x;
    float* xp = x + (size_t)row*DD;
    const float* sp = sub + (size_t)row*DD;
    const float* cp = ca + (size_t)(row >> 8)*DD;
    int t = threadIdx.x;
    __shared__ float red[8];

    float4 xv = ((const float4*)xp)[t];
    float4 sv = ((const float4*)sp)[t];
    float v[4] = {xv.x+sv.x, xv.y+sv.y, xv.z+sv.z, xv.w+sv.w};
    float y1[4];
    ln_block(v, ((const float4*)g1)[t], ((const float4*)b1)[t], t, red, y1);
    __syncthreads();

    float4 cv = ((const float4*)cp)[t];
    float v2[4] = {y1[0]+cv.x, y1[1]+cv.y, y1[2]+cv.z, y1[3]+cv.w};
    float o[4];
    ln_block(v2, ((const float4*)g2)[t], ((const float4*)b2)[t], t, red, o);
    ((float4*)xp)[t] = make_float4(o[0], o[1], o[2], o[3]);
    uint32_t h0, l0, h1, l1;
    split2(o[0], o[1], h0, l0);
    split2(o[2], o[3], h1, l1);
    ((uint2*)(xhi + (size_t)row*DD))[t] = make_uint2(h0, h1);
    ((uint2*)(xlo + (size_t)row*DD))[t] = make_uint2(l0, l1);
}

// ---------------------------------------------------------------------------
// Launch
// ---------------------------------------------------------------------------
extern "C" void kernel_launch(void* const* d_in, const int* in_sizes, int n_in,
                              void* d_out, int out_size) {
    const float* z      = (const float*)d_in[0];
    const int*   tgt    = (const int*)  d_in[1];
    const float* emb    = (const float*)d_in[2];
    const float* pos    = (const float*)d_in[3];
    const float* proj_w = (const float*)d_in[4];
    const float* proj_b = (const float*)d_in[5];
    const float* sa_w   = (const float*)d_in[6];
    const float* sa_b   = (const float*)d_in[7];
    const float* sa_ow  = (const float*)d_in[8];
    const float* sa_ob  = (const float*)d_in[9];
    const float* ca_w   = (const float*)d_in[10];
    const float* ca_b   = (const float*)d_in[11];
    const float* ca_ow  = (const float*)d_in[12];
    const float* ca_ob  = (const float*)d_in[13];
    const float* ln1_s  = (const float*)d_in[14];
    const float* ln1_b  = (const float*)d_in[15];
    const float* ln2_s  = (const float*)d_in[16];
    const float* ln2_b  = (const float*)d_in[17];
    const float* ln3_s  = (const float*)d_in[18];
    const float* ln3_b  = (const float*)d_in[19];
    const float* ff1_w  = (const float*)d_in[20];
    const float* ff1_b  = (const float*)d_in[21];
    const float* ff2_w  = (const float*)d_in[22];
    const float* ff2_b  = (const float*)d_in[23];
    const float* fc_w   = (const float*)d_in[24];
    const float* fc_b   = (const float*)d_in[25];
    float* out = (float*)d_out;

    float *x, *sub, *mem, *cav, *ca;
    __nv_bfloat16 *ahi, *alo, *qhi, *qlo, *fhi, *flo, *whi, *wlo;
    cudaGetSymbolAddress((void**)&x,   g_x);
    cudaGetSymbolAddress((void**)&sub, g_sub);
    cudaGetSymbolAddress((void**)&mem, g_mem);
    cudaGetSymbolAddress((void**)&cav, g_cav);
    cudaGetSymbolAddress((void**)&ca,  g_ca);
    cudaGetSymbolAddress((void**)&ahi, g_ahi);
    cudaGetSymbolAddress((void**)&alo, g_alo);
    cudaGetSymbolAddress((void**)&qhi, g_qhi);
    cudaGetSymbolAddress((void**)&qlo, g_qlo);
    cudaGetSymbolAddress((void**)&fhi, g_fhi);
    cudaGetSymbolAddress((void**)&flo, g_flo);
    cudaGetSymbolAddress((void**)&whi, g_whi);
    cudaGetSymbolAddress((void**)&wlo, g_wlo);

    cudaFuncSetAttribute(gemm_hmma2,
                         cudaFuncAttributeMaxDynamicSharedMemorySize, G2SMEM);
    cudaFuncSetAttribute(attn_hmma,
                         cudaFuncAttributeMaxDynamicSharedMemorySize, ATT_SMEM);

    // ---- weight conversion ----
    conv_pair<<<6*3*DD*DD/1024, 256>>>(sa_w,  whi + O_SAW,  wlo + O_SAW);
    conv_pair<<<6*DD*DD/1024,   256>>>(sa_ow, whi + O_SAOW, wlo + O_SAOW);
    conv_pair<<<6*DFF*DD/1024,  256>>>(ff1_w, whi + O_FF1,  wlo + O_FF1);
    conv_pair<<<6*DD*DFF/1024,  256>>>(ff2_w, whi + O_FF2,  wlo + O_FF2);
    conv_pair<<<VV*DD/1024,     256>>>(fc_w,  whi + O_FC,   wlo + O_FC);

    // ---- embedding + memory projection ----
    embed_kernel<<<M_TOK, 128>>>(tgt, emb, pos, x, ahi, alo);
    gemm_nt_b<<<dim3(DD/128, 1, 1), 256>>>(z, 0, proj_w, 0, proj_b, 0,
                                           mem, 0, BB, DD, DD);

    // ---- batched cross-attention vectors (all layers) ----
    gemm_nt_b<<<dim3(DD/128, 1, LL), 256>>>(
        mem, 0,
        ca_w + (size_t)2*DD*DD, (size_t)3*DD*DD,
        ca_b + 2*DD, (size_t)3*DD,
        cav, (size_t)BB*DD, BB, DD, DD);
    gemm_nt_b<<<dim3(DD/128, 1, LL), 256>>>(
        cav, (size_t)BB*DD,
        ca_ow, (size_t)DD*DD,
        ca_ob, (size_t)DD,
        ca, (size_t)BB*DD, BB, DD, DD);

    for (int l = 0; l < LL; l++) {
        const float* sabl  = sa_b  + (size_t)l*3*DD;
        const float* saobl = sa_ob + (size_t)l*DD;
        size_t o_qkv = O_SAW  + (size_t)l*3*DD*DD;
        size_t o_ow  = O_SAOW + (size_t)l*DD*DD;
        size_t o_ff1 = O_FF1  + (size_t)l*DFF*DD;
        size_t o_ff2 = O_FF2  + (size_t)l*DD*DFF;

        // self-attention
        gemm_hmma2<<<dim3(12, 64), 256, G2SMEM>>>(ahi, alo, whi + o_qkv,
                                                  wlo + o_qkv, sabl, nullptr,
                                                  qhi, qlo, 3*DD, DD, 0, 1);
        attn_hmma<<<BB*HH*4, 256, ATT_SMEM>>>(qhi, qlo, ahi, alo);
        gemm_hmma2<<<dim3(4, 64), 256, G2SMEM>>>(ahi, alo, whi + o_ow,
                                                 wlo + o_ow, saobl, sub,
                                                 nullptr, nullptr, DD, DD, 0, 0);
        // fused ln1 + ln2 (cross-attn residual precomputed)
        add_ln2_kernel<<<M_TOK, 128>>>(x, sub, ca + (size_t)l*BB*DD,
                                       ln1_s + l*DD, ln1_b + l*DD,
                                       ln2_s + l*DD, ln2_b + l*DD, ahi, alo);

        // feed-forward
        gemm_hmma2<<<dim3(16, 64), 256, G2SMEM>>>(ahi, alo, whi + o_ff1,
                                                  wlo + o_ff1, ff1_b + l*DFF,
                                                  nullptr, fhi, flo,
                                                  DFF, DD, 1, 1);
        gemm_hmma2<<<dim3(4, 64), 256, G2SMEM>>>(fhi, flo, whi + o_ff2,
                                                 wlo + o_ff2, ff2_b + l*DD,
                                                 sub, nullptr, nullptr,
                                                 DD, DFF, 0, 0);
        add_ln_kernel<<<M_TOK, 128>>>(x, sub, ln3_s + l*DD, ln3_b + l*DD,
                                      ahi, alo);
    }

    // final classifier
    gemm_hmma2<<<dim3(1, 64), 256, G2SMEM>>>(ahi, alo, whi + O_FC, wlo + O_FC,
                                             fc_b, out, nullptr, nullptr,
                                             VV, DD, 0, 0);
}